// round 9
// baseline (speedup 1.0000x reference)
#include <cuda_runtime.h>
#include <cuda_bf16.h>
#include <math.h>
#include <stdint.h>

// Problem constants
#define BATCH 2
#define TSEQ  4096
#define DIM   2048
#define NH    16
#define HD    128
#define M1    (BATCH*TSEQ)      // 8192
#define N_QKV (3*DIM)           // 6144

// K-dim permutation within each 8-group: logical c -> stored 2*(c&3) | (c>>2)
// Pairs (tg, tg+4) become adjacent (2tg, 2tg+1) -> LDS.64 fragment loads.
#define P8(c) (((((c)&3)<<1) | (((c)>>2)&1)))

// ---------------- scratch (static device globals; no allocs allowed) ----------
__device__ float g_qkv[(size_t)M1 * N_QKV];
__device__ float g_q[(size_t)BATCH*NH*TSEQ*HD];
__device__ float g_k[(size_t)BATCH*NH*TSEQ*HD];
__device__ float g_v[(size_t)BATCH*NH*TSEQ*HD];
__device__ float g_att[(size_t)M1 * DIM];
__device__ float g_ctab[(size_t)TSEQ * HD];
__device__ float g_stab[(size_t)TSEQ * HD];
__device__ float g_xr[(size_t)M1 * DIM];
__device__ float g_wqkvr[(size_t)N_QKV * DIM];
__device__ float g_wprojr[(size_t)DIM * DIM];

// ---------------- helpers -----------------------------------------------------
__device__ __forceinline__ uint32_t f2tf32(float x) {
    uint32_t u;
    asm("cvt.rna.tf32.f32 %0, %1;" : "=r"(u) : "f"(x));
    return u;
}

__device__ __forceinline__ void mma_tf32(float* d, const uint32_t* a, const uint32_t* b) {
    asm volatile(
        "mma.sync.aligned.m16n8k8.row.col.f32.tf32.tf32.f32 "
        "{%0,%1,%2,%3}, {%4,%5,%6,%7}, {%8,%9}, {%0,%1,%2,%3};"
        : "+f"(d[0]), "+f"(d[1]), "+f"(d[2]), "+f"(d[3])
        : "r"(a[0]), "r"(a[1]), "r"(a[2]), "r"(a[3]), "r"(b[0]), "r"(b[1]));
}

__device__ __forceinline__ uint32_t smem_u32(const void* p) {
    uint32_t a;
    asm("{ .reg .u64 t; cvta.to.shared.u64 t, %1; cvt.u32.u64 %0, t; }" : "=r"(a) : "l"(p));
    return a;
}
__device__ __forceinline__ void cp_async16(uint32_t saddr, const void* gaddr) {
    asm volatile("cp.async.cg.shared.global [%0], [%1], 16;" :: "r"(saddr), "l"(gaddr));
}
#define CP_COMMIT() asm volatile("cp.async.commit_group;" ::: "memory")
#define CP_WAIT1()  asm volatile("cp.async.wait_group 1;" ::: "memory")
#define CP_WAIT2()  asm volatile("cp.async.wait_group 2;" ::: "memory")

// ---------------- cos/sin table ----------------------------------------------
__global__ void build_tab(float* __restrict__ ct, float* __restrict__ st) {
    int t = blockIdx.x;
    int j = threadIdx.x;
    int m = j & 63;
    float base = (float)pow(10000.0, (double)m / 64.0);
    float invf = 1.0f / base;
    float ang = (float)t * invf;
    ct[t*HD + j] = cosf(ang);
    st[t*HD + j] = sinf(ang);
}

// ---------------- tf32 pre-round + K-permute pass ----------------------------
__global__ void round_tf32(const float* __restrict__ in, float* __restrict__ out) {
    size_t i = ((size_t)blockIdx.x * 256 + threadIdx.x) * 4;
    float4 v = *(const float4*)(in + i);
    size_t base = i & ~(size_t)7;
    int c0 = (int)(i & 7);           // 0 or 4
    out[base + P8(c0+0)] = __uint_as_float(f2tf32(v.x));
    out[base + P8(c0+1)] = __uint_as_float(f2tf32(v.y));
    out[base + P8(c0+2)] = __uint_as_float(f2tf32(v.z));
    out[base + P8(c0+3)] = __uint_as_float(f2tf32(v.w));
}

// ---------------- cp.async pipelined tf32 GEMM: C = A * B^T -------------------
// A,B stored K-permuted (P8 groups). 128x256 tile, BK=32, 3 stages, 256 thr.
#define BM 128
#define BN 256
#define BK2 32
#define STAGES 3
#define ASTR 36
#define GEMM2_SMEM (STAGES * (BM + BN) * ASTR * 4)   // 165888 B

__global__ __launch_bounds__(256, 1) void gemm_mma2(
    const float* __restrict__ A, const float* __restrict__ B,
    float* __restrict__ C, int M, int N, int K)
{
    extern __shared__ float smem[];
    uint32_t sbase = smem_u32(smem);
    const uint32_t boff = STAGES * BM * ASTR;

    int tid  = threadIdx.x;
    int wid  = tid >> 5, lane = tid & 31;
    int g    = lane >> 2, tg = lane & 3;
    int wm   = wid >> 2, wn = wid & 3;
    int m0   = blockIdx.y * BM;
    int n0   = blockIdx.x * BN;
    int lrow = tid >> 3;           // 0..31
    int lc4  = (tid & 7) << 2;     // 0..28

    float acc[4][8][4];
#pragma unroll
    for (int i = 0; i < 4; i++)
#pragma unroll
        for (int j = 0; j < 8; j++)
#pragma unroll
            for (int r = 0; r < 4; r++) acc[i][j][r] = 0.f;

    const int nch = K / BK2;

    auto issue = [&](int ch, int s, bool pred) {
        if (pred) {
            const float* Ag = A + (size_t)m0 * K + ch * BK2;
            const float* Bg = B + (size_t)n0 * K + ch * BK2;
            uint32_t as = sbase + (uint32_t)(s * BM * ASTR) * 4u;
            uint32_t bs = sbase + (boff + (uint32_t)(s * BN * ASTR)) * 4u;
#pragma unroll
            for (int e = 0; e < 4; e++) {
                int r = lrow + e * 32;
                cp_async16(as + (uint32_t)(r * ASTR + lc4) * 4u, Ag + (size_t)r * K + lc4);
            }
#pragma unroll
            for (int e = 0; e < 8; e++) {
                int r = lrow + e * 32;
                cp_async16(bs + (uint32_t)(r * ASTR + lc4) * 4u, Bg + (size_t)r * K + lc4);
            }
        }
        CP_COMMIT();
    };

    issue(0, 0, true);
    issue(1, 1, 1 < nch);

    for (int ch = 0; ch < nch; ch++) {
        CP_WAIT1();
        __syncthreads();
        issue(ch + 2, (ch + 2) % STAGES, ch + 2 < nch);

        int s = ch % STAGES;
        const float* asf = smem + s * BM * ASTR;
        const float* bsf = smem + boff + s * BN * ASTR;

#pragma unroll
        for (int ks = 0; ks < BK2; ks += 8) {
            uint32_t afr[4][4];
#pragma unroll
            for (int mi = 0; mi < 4; mi++) {
                int mr = wm * 64 + mi * 16;
                float2 fa0 = *(const float2*)(asf + (mr + g    ) * ASTR + ks + 2*tg);
                float2 fa1 = *(const float2*)(asf + (mr + g + 8) * ASTR + ks + 2*tg);
                afr[mi][0] = __float_as_uint(fa0.x);
                afr[mi][1] = __float_as_uint(fa1.x);
                afr[mi][2] = __float_as_uint(fa0.y);
                afr[mi][3] = __float_as_uint(fa1.y);
            }
            uint32_t bfr[8][2];
#pragma unroll
            for (int nj = 0; nj < 8; nj++) {
                int nr = wn * 64 + nj * 8;
                float2 fb = *(const float2*)(bsf + (nr + g) * ASTR + ks + 2*tg);
                bfr[nj][0] = __float_as_uint(fb.x);
                bfr[nj][1] = __float_as_uint(fb.y);
            }
#pragma unroll
            for (int mi = 0; mi < 4; mi++)
#pragma unroll
                for (int nj = 0; nj < 8; nj++)
                    mma_tf32(acc[mi][nj], afr[mi], bfr[nj]);
        }
        __syncthreads();
    }

#pragma unroll
    for (int mi = 0; mi < 4; mi++) {
#pragma unroll
        for (int nj = 0; nj < 8; nj++) {
            int row = m0 + wm * 64 + mi * 16 + g;
            int col = n0 + wn * 64 + nj * 8 + tg * 2;
            *(float2*)(C + (size_t)row * N + col) =
                make_float2(acc[mi][nj][0], acc[mi][nj][1]);
            *(float2*)(C + (size_t)(row + 8) * N + col) =
                make_float2(acc[mi][nj][2], acc[mi][nj][3]);
        }
    }
}

// ---------------- RoPE + head split (Q/K d-permuted, V t-row-permuted) -------
__global__ void rope_split(const float* __restrict__ qkv,
                           const float* __restrict__ ct, const float* __restrict__ st,
                           float* __restrict__ Qo, float* __restrict__ Ko,
                           float* __restrict__ Vo)
{
    int h  = blockIdx.x;
    int bt = blockIdx.y;
    int j  = threadIdx.x;
    int b  = bt >> 12;
    int t  = bt & (TSEQ - 1);

    size_t base = (size_t)bt * N_QKV + h * HD;
    float c = ct[t*HD + j];
    float s = st[t*HD + j];

    float xq  = qkv[base + j];
    float xqp = qkv[base + (j ^ 1)];
    float rq  = (j & 1) ? xqp : -xqp;

    float xk  = qkv[base + DIM + j];
    float xkp = qkv[base + DIM + (j ^ 1)];
    float rk  = (j & 1) ? xkp : -xkp;

    float xv  = qkv[base + 2*DIM + j];

    int jp = (j & ~7) | P8(j & 7);                       // permuted d slot
    int tp = (t & ~7) | P8(t & 7);                       // permuted t slot (V rows)
    size_t qb = ((size_t)(b*NH + h) * TSEQ + t) * HD + jp;
    Qo[qb] = __uint_as_float(f2tf32(xq * c + rq * s));
    Ko[qb] = __uint_as_float(f2tf32(xk * c + rk * s));
    Vo[((size_t)(b*NH + h) * TSEQ + tp) * HD + j] = __uint_as_float(f2tf32(xv));
}

// ---------------- tf32 mma flash attention (causal, cp.async pipelined) ------
#define FQ 128
#define FK 64
#define QSTR 132
#define KSTR 132
#define VSTR 136
#define PSTR 68
#define OFF_Q  0
#define OFF_K0 (OFF_Q  + FQ*QSTR)    // 16896
#define OFF_K1 (OFF_K0 + FK*KSTR)    // 25344
#define OFF_V  (OFF_K1 + FK*KSTR)    // 33792
#define OFF_P  (OFF_V  + FK*VSTR)    // 42496
#define FLASH2_FLOATS (OFF_P + FQ*PSTR)  // 51200
#define FLASH2_BYTES (FLASH2_FLOATS * 4) // 204800

__global__ __launch_bounds__(256, 1) void flash_mma(
    const float* __restrict__ Q, const float* __restrict__ K,
    const float* __restrict__ V, float* __restrict__ Oatt)
{
    extern __shared__ float sm[];
    float* Qs = sm + OFF_Q;
    float* Vs = sm + OFF_V;
    float* Ps = sm + OFF_P;
    uint32_t sbase = smem_u32(sm);

    int qi  = blockIdx.x;
    int bh  = blockIdx.y;
    int tid = threadIdx.x;
    int w    = tid >> 5;
    int lane = tid & 31;
    int g    = lane >> 2;
    int tg   = lane & 3;

    const float* Qp = Q + (size_t)bh * TSEQ * HD;
    const float* Kp = K + (size_t)bh * TSEQ * HD;
    const float* Vp = V + (size_t)bh * TSEQ * HD;

    int q0 = qi * FQ;
    int nkt = 2 * qi + 2;

    auto issueK = [&](int kt, bool pred) {
        if (pred) {
            int k0 = kt * FK;
            uint32_t kb = sbase + (uint32_t)((kt & 1) ? OFF_K1 : OFF_K0) * 4u;
#pragma unroll
            for (int e = 0; e < 8; e++) {
                int idx = tid + e * 256;
                int r  = idx >> 5;
                int c4 = (idx & 31) << 2;
                cp_async16(kb + (uint32_t)(r * KSTR + c4) * 4u,
                           Kp + (size_t)(k0 + r) * HD + c4);
            }
        }
        CP_COMMIT();
    };
    auto issueV = [&](int kt) {
        int k0 = kt * FK;
        uint32_t vb = sbase + (uint32_t)OFF_V * 4u;
#pragma unroll
        for (int e = 0; e < 8; e++) {
            int idx = tid + e * 256;
            int r  = idx >> 5;
            int c4 = (idx & 31) << 2;
            cp_async16(vb + (uint32_t)(r * VSTR + c4) * 4u,
                       Vp + (size_t)(k0 + r) * HD + c4);
        }
        CP_COMMIT();
    };

    issueK(0, true);

    // load Q tile (already tf32-rounded + d-permuted)
#pragma unroll
    for (int e = 0; e < 16; e++) {
        int idx = tid + e * 256;
        int r  = idx >> 5;
        int c4 = (idx & 31) << 2;
        float4 v = *(const float4*)(Qp + (size_t)(q0 + r) * HD + c4);
        *(float4*)(Qs + r * QSTR + c4) = v;
    }

    float o[16][4];
#pragma unroll
    for (int i = 0; i < 16; i++)
#pragma unroll
        for (int j = 0; j < 4; j++) o[i][j] = 0.f;

    float m0r = -1e30f, m1r = -1e30f;
    float l0 = 0.f, l1 = 0.f;
    const float scale = 0.08838834764831845f;

    int rowbase = q0 + w * 16;
    int r0g = rowbase + g;
    int r1g = rowbase + g + 8;

    float s[8][4];

    for (int kt = 0; kt < nkt; kt++) {
        int k0 = kt * FK;
        const float* Ks = sm + ((kt & 1) ? OFF_K1 : OFF_K0);

        issueV(kt);
        issueK(kt + 1, kt + 1 < nkt);
        CP_WAIT2();                 // K(kt) complete; V(kt), K(kt+1) in flight
        __syncthreads();

        bool active = (k0 <= rowbase + 15);
        if (active) {
            // ---- S = Q K^T (d-permuted operands, consistent -> S exact) ----
#pragma unroll
            for (int nj = 0; nj < 8; nj++)
#pragma unroll
                for (int r = 0; r < 4; r++) s[nj][r] = 0.f;

#pragma unroll
            for (int ks = 0; ks < 16; ks++) {
                uint32_t a[4];
                float2 qa0 = *(const float2*)(Qs + (rowbase - q0 + g    ) * QSTR + ks*8 + 2*tg);
                float2 qa1 = *(const float2*)(Qs + (rowbase - q0 + g + 8) * QSTR + ks*8 + 2*tg);
                a[0] = __float_as_uint(qa0.x);
                a[1] = __float_as_uint(qa1.x);
                a[2] = __float_as_uint(qa0.y);
                a[3] = __float_as_uint(qa1.y);
#pragma unroll
                for (int nj = 0; nj < 8; nj++) {
                    float2 kb = *(const float2*)(Ks + (nj*8 + g) * KSTR + ks*8 + 2*tg);
                    uint32_t b[2];
                    b[0] = __float_as_uint(kb.x);
                    b[1] = __float_as_uint(kb.y);
                    mma_tf32(s[nj], a, b);
                }
            }

            // ---- causal mask (K rows natural order) ----
            if (k0 + FK - 1 > rowbase) {
#pragma unroll
                for (int nj = 0; nj < 8; nj++) {
                    int c = k0 + nj*8 + 2*tg;
                    if (c     > r0g) s[nj][0] = -1e30f;
                    if (c + 1 > r0g) s[nj][1] = -1e30f;
                    if (c     > r1g) s[nj][2] = -1e30f;
                    if (c + 1 > r1g) s[nj][3] = -1e30f;
                }
            }

            // ---- online softmax ----
            float mx0 = -1e30f, mx1 = -1e30f;
#pragma unroll
            for (int nj = 0; nj < 8; nj++) {
                mx0 = fmaxf(mx0, fmaxf(s[nj][0], s[nj][1]));
                mx1 = fmaxf(mx1, fmaxf(s[nj][2], s[nj][3]));
            }
            mx0 = fmaxf(mx0, __shfl_xor_sync(0xffffffff, mx0, 1));
            mx0 = fmaxf(mx0, __shfl_xor_sync(0xffffffff, mx0, 2));
            mx1 = fmaxf(mx1, __shfl_xor_sync(0xffffffff, mx1, 1));
            mx1 = fmaxf(mx1, __shfl_xor_sync(0xffffffff, mx1, 2));

            float mn0 = fmaxf(m0r, mx0);
            float mn1 = fmaxf(m1r, mx1);
            float al0 = __expf((m0r - mn0) * scale);
            float al1 = __expf((m1r - mn1) * scale);
            m0r = mn0; m1r = mn1;

            float sum0 = 0.f, sum1 = 0.f;
#pragma unroll
            for (int nj = 0; nj < 8; nj++) {
                float p0 = __expf((s[nj][0] - mn0) * scale);
                float p1 = __expf((s[nj][1] - mn0) * scale);
                float p2 = __expf((s[nj][2] - mn1) * scale);
                float p3 = __expf((s[nj][3] - mn1) * scale);
                s[nj][0] = p0; s[nj][1] = p1; s[nj][2] = p2; s[nj][3] = p3;
                sum0 += p0 + p1; sum1 += p2 + p3;
            }
            sum0 += __shfl_xor_sync(0xffffffff, sum0, 1);
            sum0 += __shfl_xor_sync(0xffffffff, sum0, 2);
            sum1 += __shfl_xor_sync(0xffffffff, sum1, 1);
            sum1 += __shfl_xor_sync(0xffffffff, sum1, 2);

            l0 = l0 * al0 + sum0;
            l1 = l1 * al1 + sum1;

#pragma unroll
            for (int t2 = 0; t2 < 16; t2++) {
                o[t2][0] *= al0; o[t2][1] *= al0;
                o[t2][2] *= al1; o[t2][3] *= al1;
            }

            // ---- write P with permuted columns (matches V row permutation) --
            int pr0 = (rowbase - q0 + g) * PSTR;
            int pr1 = (rowbase - q0 + g + 8) * PSTR;
#pragma unroll
            for (int nj = 0; nj < 8; nj++) {
                int cb = nj*8;
                Ps[pr0 + cb + P8(2*tg    )] = __uint_as_float(f2tf32(s[nj][0]));
                Ps[pr0 + cb + P8(2*tg + 1)] = __uint_as_float(f2tf32(s[nj][1]));
                Ps[pr1 + cb + P8(2*tg    )] = __uint_as_float(f2tf32(s[nj][2]));
                Ps[pr1 + cb + P8(2*tg + 1)] = __uint_as_float(f2tf32(s[nj][3]));
            }
        }

        CP_WAIT1();                 // V(kt) complete; K(kt+1) may be in flight
        __syncthreads();

        if (active) {
            int pr0 = (rowbase - q0 + g) * PSTR;
            int pr1 = (rowbase - q0 + g + 8) * PSTR;
#pragma unroll
            for (int ks2 = 0; ks2 < 8; ks2++) {
                uint32_t a2[4];
                float2 pa0 = *(const float2*)(Ps + pr0 + ks2*8 + 2*tg);
                float2 pa1 = *(const float2*)(Ps + pr1 + ks2*8 + 2*tg);
                a2[0] = __float_as_uint(pa0.x);
                a2[1] = __float_as_uint(pa1.x);
                a2[2] = __float_as_uint(pa0.y);
                a2[3] = __float_as_uint(pa1.y);
#pragma unroll
                for (int nj2 = 0; nj2 < 16; nj2++) {
                    uint32_t b2[2];
                    // logical V rows tg / tg+4 live at permuted slots 2tg / 2tg+1
                    b2[0] = __float_as_uint(Vs[(ks2*8 + 2*tg    ) * VSTR + nj2*8 + g]);
                    b2[1] = __float_as_uint(Vs[(ks2*8 + 2*tg + 1) * VSTR + nj2*8 + g]);
                    mma_tf32(o[nj2], a2, b2);
                }
            }
        }
        __syncthreads();            // V buffer + K stage free for next iteration
    }

    // epilogue: normalize + tf32-round + write att K-PERMUTED (proj GEMM A)
    float inv0 = 1.0f / l0;
    float inv1 = 1.0f / l1;
    int b = bh >> 4, h = bh & 15;
#pragma unroll
    for (int nj2 = 0; nj2 < 16; nj2++) {
        int colb = h * HD + nj2*8;
        size_t rb0 = (size_t)(b*TSEQ + r0g) * DIM + colb;
        size_t rb1 = (size_t)(b*TSEQ + r1g) * DIM + colb;
        Oatt[rb0 + P8(2*tg    )] = __uint_as_float(f2tf32(o[nj2][0] * inv0));
        Oatt[rb0 + P8(2*tg + 1)] = __uint_as_float(f2tf32(o[nj2][1] * inv0));
        Oatt[rb1 + P8(2*tg    )] = __uint_as_float(f2tf32(o[nj2][2] * inv1));
        Oatt[rb1 + P8(2*tg + 1)] = __uint_as_float(f2tf32(o[nj2][3] * inv1));
    }
}

// ---------------- launch ------------------------------------------------------
extern "C" void kernel_launch(void* const* d_in, const int* in_sizes, int n_in,
                              void* d_out, int out_size) {
    const float* x      = (const float*)d_in[0];
    const float* w_qkv  = (const float*)d_in[1];
    const float* w_proj = (const float*)d_in[2];
    float* out = (float*)d_out;

    float *qkv, *q, *k, *v, *att, *ct, *st, *xr, *wqkvr, *wprojr;
    cudaGetSymbolAddress((void**)&qkv,    g_qkv);
    cudaGetSymbolAddress((void**)&q,      g_q);
    cudaGetSymbolAddress((void**)&k,      g_k);
    cudaGetSymbolAddress((void**)&v,      g_v);
    cudaGetSymbolAddress((void**)&att,    g_att);
    cudaGetSymbolAddress((void**)&ct,     g_ctab);
    cudaGetSymbolAddress((void**)&st,     g_stab);
    cudaGetSymbolAddress((void**)&xr,     g_xr);
    cudaGetSymbolAddress((void**)&wqkvr,  g_wqkvr);
    cudaGetSymbolAddress((void**)&wprojr, g_wprojr);

    cudaFuncSetAttribute(gemm_mma2, cudaFuncAttributeMaxDynamicSharedMemorySize, GEMM2_SMEM);
    cudaFuncSetAttribute(flash_mma, cudaFuncAttributeMaxDynamicSharedMemorySize, FLASH2_BYTES);

    build_tab<<<TSEQ, HD>>>(ct, st);

    round_tf32<<<(M1*(size_t)DIM)/(256*4), 256>>>(x, xr);
    round_tf32<<<((size_t)N_QKV*DIM)/(256*4), 256>>>(w_qkv, wqkvr);
    round_tf32<<<((size_t)DIM*DIM)/(256*4), 256>>>(w_proj, wprojr);

    gemm_mma2<<<dim3(N_QKV/BN, M1/BM), 256, GEMM2_SMEM>>>(xr, wqkvr, qkv, M1, N_QKV, DIM);

    rope_split<<<dim3(NH, M1), HD>>>(qkv, ct, st, q, k, v);

    flash_mma<<<dim3(TSEQ/FQ, BATCH*NH), 256, FLASH2_BYTES>>>(q, k, v, att);

    gemm_mma2<<<dim3(DIM/BN, M1/BM), 256, GEMM2_SMEM>>>(att, wprojr, out, M1, DIM, DIM);
}

// round 11
// speedup vs baseline: 2.0516x; 2.0516x over previous
#include <cuda_runtime.h>
#include <cuda_fp16.h>
#include <math.h>
#include <stdint.h>

// Problem constants
#define BATCH 2
#define TSEQ  4096
#define DIM   2048
#define NH    16
#define HD    128
#define M1    (BATCH*TSEQ)      // 8192
#define N_QKV (3*DIM)           // 6144

// ---------------- scratch (static device globals; no allocs allowed) ----------
__device__ float  g_qkv[(size_t)M1 * N_QKV];           // fp32 qkv (GEMM1 out)
__device__ __half g_xh[(size_t)M1 * DIM];
__device__ __half g_wqkvh[(size_t)N_QKV * DIM];
__device__ __half g_wprojh[(size_t)DIM * DIM];
__device__ __half g_qh[(size_t)BATCH*NH*TSEQ*HD];      // [bh][t][d]
__device__ __half g_kh[(size_t)BATCH*NH*TSEQ*HD];      // [bh][t][d]
__device__ __half g_vth[(size_t)BATCH*NH*HD*TSEQ];     // [bh][d][t]  (transposed)
__device__ __half g_atth[(size_t)M1 * DIM];
__device__ float  g_ctab[(size_t)TSEQ * HD];
__device__ float  g_stab[(size_t)TSEQ * HD];

// ---------------- helpers -----------------------------------------------------
__device__ __forceinline__ void mma_f16(float* d, const uint32_t* a, const uint32_t* b) {
    asm volatile(
        "mma.sync.aligned.m16n8k16.row.col.f32.f16.f16.f32 "
        "{%0,%1,%2,%3}, {%4,%5,%6,%7}, {%8,%9}, {%0,%1,%2,%3};"
        : "+f"(d[0]), "+f"(d[1]), "+f"(d[2]), "+f"(d[3])
        : "r"(a[0]), "r"(a[1]), "r"(a[2]), "r"(a[3]), "r"(b[0]), "r"(b[1]));
}

__device__ __forceinline__ uint32_t smem_u32(const void* p) {
    uint32_t a;
    asm("{ .reg .u64 t; cvta.to.shared.u64 t, %1; cvt.u32.u64 %0, t; }" : "=r"(a) : "l"(p));
    return a;
}
__device__ __forceinline__ void cp_async16(uint32_t saddr, const void* gaddr) {
    asm volatile("cp.async.cg.shared.global [%0], [%1], 16;" :: "r"(saddr), "l"(gaddr));
}
#define CP_COMMIT() asm volatile("cp.async.commit_group;" ::: "memory")
#define CP_WAIT1()  asm volatile("cp.async.wait_group 1;" ::: "memory")
#define CP_WAIT2()  asm volatile("cp.async.wait_group 2;" ::: "memory")

__device__ __forceinline__ uint32_t h2u(__half2 h) {
    union { __half2 h; uint32_t u; } c; c.h = h; return c.u;
}

// ---------------- cos/sin table ----------------------------------------------
__global__ void build_tab(float* __restrict__ ct, float* __restrict__ st) {
    int t = blockIdx.x;
    int j = threadIdx.x;
    int m = j & 63;
    float base = (float)pow(10000.0, (double)m / 64.0);
    float invf = 1.0f / base;
    float ang = (float)t * invf;
    ct[t*HD + j] = cosf(ang);
    st[t*HD + j] = sinf(ang);
}

// ---------------- fp32 -> fp16 pass (8 elems/thread) --------------------------
__global__ void round_half(const float* __restrict__ in, __half* __restrict__ out) {
    size_t i = ((size_t)blockIdx.x * 256 + threadIdx.x) * 8;
    float4 v0 = *(const float4*)(in + i);
    float4 v1 = *(const float4*)(in + i + 4);
    uint4 u;
    u.x = h2u(__floats2half2_rn(v0.x, v0.y));
    u.y = h2u(__floats2half2_rn(v0.z, v0.w));
    u.z = h2u(__floats2half2_rn(v1.x, v1.y));
    u.w = h2u(__floats2half2_rn(v1.z, v1.w));
    *(uint4*)(out + i) = u;
}

// ---------------- fp16 cp.async pipelined GEMM: C = A * B^T -------------------
// A[M,K], B[N,K] half; C[M,N] float. 128x128 tile, BK=32, 3 stages, 8 warps 2x4.
#define BM 128
#define BN 128
#define BKH 32
#define STAGES 3
#define HSTR 40
#define GEMMH_SMEM (STAGES * (BM + BN) * HSTR * 2)    // 61440 B

__global__ __launch_bounds__(256, 2) void gemm_h(
    const __half* __restrict__ A, const __half* __restrict__ B,
    float* __restrict__ C, int M, int N, int K)
{
    extern __shared__ __half hsm[];
    uint32_t sbase = smem_u32(hsm);
    const uint32_t boff = STAGES * BM * HSTR;          // halves

    int tid  = threadIdx.x;
    int wid  = tid >> 5, lane = tid & 31;
    int g    = lane >> 2, tg = lane & 3;
    int wm   = wid >> 2, wn = wid & 3;
    int m0   = blockIdx.y * BM;
    int n0   = blockIdx.x * BN;
    int lrow = tid >> 2;              // 0..63
    int lc8  = (tid & 3) << 3;        // 0,8,16,24 (halves)

    float acc[4][4][4];
#pragma unroll
    for (int i = 0; i < 4; i++)
#pragma unroll
        for (int j = 0; j < 4; j++)
#pragma unroll
            for (int r = 0; r < 4; r++) acc[i][j][r] = 0.f;

    const int nch = K / BKH;

    auto issue = [&](int ch, int s, bool pred) {
        if (pred) {
            const __half* Ag = A + (size_t)m0 * K + ch * BKH;
            const __half* Bg = B + (size_t)n0 * K + ch * BKH;
            uint32_t as = sbase + (uint32_t)(s * BM * HSTR) * 2u;
            uint32_t bs = sbase + (boff + (uint32_t)(s * BN * HSTR)) * 2u;
#pragma unroll
            for (int e = 0; e < 2; e++) {
                int r = lrow + e * 64;
                cp_async16(as + (uint32_t)(r * HSTR + lc8) * 2u, Ag + (size_t)r * K + lc8);
                cp_async16(bs + (uint32_t)(r * HSTR + lc8) * 2u, Bg + (size_t)r * K + lc8);
            }
        }
        CP_COMMIT();
    };

    issue(0, 0, true);
    issue(1, 1, 1 < nch);

    for (int ch = 0; ch < nch; ch++) {
        CP_WAIT1();
        __syncthreads();
        issue(ch + 2, (ch + 2) % STAGES, ch + 2 < nch);

        int s = ch % STAGES;
        const __half* asf = hsm + s * BM * HSTR;
        const __half* bsf = hsm + boff + s * BN * HSTR;

#pragma unroll
        for (int ks = 0; ks < BKH; ks += 16) {
            uint32_t afr[4][4];
#pragma unroll
            for (int mi = 0; mi < 4; mi++) {
                int mr = wm * 64 + mi * 16;
                afr[mi][0] = *(const uint32_t*)(asf + (mr + g    ) * HSTR + ks + 2*tg);
                afr[mi][1] = *(const uint32_t*)(asf + (mr + g + 8) * HSTR + ks + 2*tg);
                afr[mi][2] = *(const uint32_t*)(asf + (mr + g    ) * HSTR + ks + 8 + 2*tg);
                afr[mi][3] = *(const uint32_t*)(asf + (mr + g + 8) * HSTR + ks + 8 + 2*tg);
            }
            uint32_t bfr[4][2];
#pragma unroll
            for (int nj = 0; nj < 4; nj++) {
                int nr = wn * 32 + nj * 8;
                bfr[nj][0] = *(const uint32_t*)(bsf + (nr + g) * HSTR + ks + 2*tg);
                bfr[nj][1] = *(const uint32_t*)(bsf + (nr + g) * HSTR + ks + 8 + 2*tg);
            }
#pragma unroll
            for (int mi = 0; mi < 4; mi++)
#pragma unroll
                for (int nj = 0; nj < 4; nj++)
                    mma_f16(acc[mi][nj], afr[mi], bfr[nj]);
        }
        __syncthreads();
    }

#pragma unroll
    for (int mi = 0; mi < 4; mi++) {
#pragma unroll
        for (int nj = 0; nj < 4; nj++) {
            int row = m0 + wm * 64 + mi * 16 + g;
            int col = n0 + wn * 32 + nj * 8 + tg * 2;
            *(float2*)(C + (size_t)row * N + col) =
                make_float2(acc[mi][nj][0], acc[mi][nj][1]);
            *(float2*)(C + (size_t)(row + 8) * N + col) =
                make_float2(acc[mi][nj][2], acc[mi][nj][3]);
        }
    }
}

// ---------------- RoPE + head split -> half Q,K ------------------------------
__global__ void rope_split(const float* __restrict__ qkv,
                           const float* __restrict__ ct, const float* __restrict__ st,
                           __half* __restrict__ Qo, __half* __restrict__ Ko)
{
    int h  = blockIdx.x;
    int bt = blockIdx.y;
    int j  = threadIdx.x;
    int b  = bt >> 12;
    int t  = bt & (TSEQ - 1);

    size_t base = (size_t)bt * N_QKV + h * HD;
    float c = ct[t*HD + j];
    float s = st[t*HD + j];

    float xq  = qkv[base + j];
    float xqp = qkv[base + (j ^ 1)];
    float rq  = (j & 1) ? xqp : -xqp;

    float xk  = qkv[base + DIM + j];
    float xkp = qkv[base + DIM + (j ^ 1)];
    float rk  = (j & 1) ? xkp : -xkp;

    size_t ob = ((size_t)(b*NH + h) * TSEQ + t) * HD + j;
    Qo[ob] = __float2half(xq * c + rq * s);
    Ko[ob] = __float2half(xk * c + rk * s);
}

// ---------------- V transpose: qkv -> Vt[bh][d][t] (half) --------------------
__global__ void vtrans(const float* __restrict__ qkv, __half* __restrict__ Vt) {
    __shared__ float tile[32][33];
    int bh = blockIdx.z;
    int b  = bh >> 4, h = bh & 15;
    int t0 = blockIdx.x * 32;
    int d0 = blockIdx.y * 32;
    int tx = threadIdx.x, ty = threadIdx.y;   // 32 x 8

#pragma unroll
    for (int i = 0; i < 4; i++) {
        int t = t0 + ty + i * 8;
        tile[ty + i*8][tx] = qkv[(size_t)(b*TSEQ + t) * N_QKV + 2*DIM + h*HD + d0 + tx];
    }
    __syncthreads();
#pragma unroll
    for (int i = 0; i < 4; i++) {
        int d = d0 + ty + i * 8;
        Vt[((size_t)bh * HD + d) * TSEQ + t0 + tx] = __float2half(tile[tx][ty + i*8]);
    }
}

// ---------------- fp16 mma flash attention (causal, cp.async pipelined) ------
// Q tile 128, K tile 64, 8 warps; warp = 16 Q rows x full K width.
#define FQ 128
#define FK 64
#define QSTR 136       // halves
#define KSTR 136
#define VSTR 72
#define PSTR 72
#define OFF_Q  0
#define OFF_K0 (OFF_Q  + FQ*QSTR)     // 17408
#define OFF_K1 (OFF_K0 + FK*KSTR)     // 26112
#define OFF_V  (OFF_K1 + FK*KSTR)     // 34816
#define OFF_P  (OFF_V  + HD*VSTR)     // 44032
#define FLASHH_HALVES (OFF_P + FQ*PSTR)   // 53248
#define FLASHH_BYTES (FLASHH_HALVES * 2)  // 106496

__global__ __launch_bounds__(256, 1) void flash_h(
    const __half* __restrict__ Q, const __half* __restrict__ K,
    const __half* __restrict__ Vt, __half* __restrict__ Oatt)
{
    extern __shared__ __half hs[];
    __half* Qs = hs + OFF_Q;
    __half* Vs = hs + OFF_V;
    __half* Ps = hs + OFF_P;
    uint32_t sbase = smem_u32(hs);

    int qi  = blockIdx.x;
    int bh  = blockIdx.y;
    int tid = threadIdx.x;
    int w    = tid >> 5;
    int lane = tid & 31;
    int g    = lane >> 2;
    int tg   = lane & 3;

    const __half* Qp  = Q  + (size_t)bh * TSEQ * HD;
    const __half* Kp  = K  + (size_t)bh * TSEQ * HD;
    const __half* Vtp = Vt + (size_t)bh * HD * TSEQ;

    int q0 = qi * FQ;
    int nkt = 2 * qi + 2;

    // K tile: [64][128] half = 1024 x 16B chunks, 4/thread
    auto issueK = [&](int kt, bool pred) {
        if (pred) {
            int k0 = kt * FK;
            uint32_t kb = sbase + (uint32_t)((kt & 1) ? OFF_K1 : OFF_K0) * 2u;
#pragma unroll
            for (int e = 0; e < 4; e++) {
                int idx = tid + e * 256;      // 0..1023
                int r  = idx >> 4;            // 0..63
                int c8 = (idx & 15) << 3;     // 0..120
                cp_async16(kb + (uint32_t)(r * KSTR + c8) * 2u,
                           Kp + (size_t)(k0 + r) * HD + c8);
            }
        }
        CP_COMMIT();
    };
    // V tile transposed: [128 d][64 t] half = 1024 chunks, 4/thread
    auto issueV = [&](int kt) {
        int k0 = kt * FK;
        uint32_t vb = sbase + (uint32_t)OFF_V * 2u;
#pragma unroll
        for (int e = 0; e < 4; e++) {
            int idx = tid + e * 256;          // 0..1023
            int d  = idx >> 3;                // 0..127
            int c8 = (idx & 7) << 3;          // 0..56
            cp_async16(vb + (uint32_t)(d * VSTR + c8) * 2u,
                       Vtp + (size_t)d * TSEQ + k0 + c8);
        }
        CP_COMMIT();
    };

    issueK(0, true);

    // load Q tile: 128x128 half = 2048 chunks, 8/thread
#pragma unroll
    for (int e = 0; e < 8; e++) {
        int idx = tid + e * 256;
        int r  = idx >> 4;
        int c8 = (idx & 15) << 3;
        uint4 v = *(const uint4*)(Qp + (size_t)(q0 + r) * HD + c8);
        *(uint4*)(Qs + r * QSTR + c8) = v;
    }

    float o[16][4];
#pragma unroll
    for (int i = 0; i < 16; i++)
#pragma unroll
        for (int j = 0; j < 4; j++) o[i][j] = 0.f;

    float m0r = -1e30f, m1r = -1e30f;
    float l0 = 0.f, l1 = 0.f;
    const float scale = 0.08838834764831845f;   // 1/sqrt(128)

    int rowbase = q0 + w * 16;
    int r0g = rowbase + g;
    int r1g = rowbase + g + 8;
    int rq = rowbase - q0;

    float s[8][4];

    for (int kt = 0; kt < nkt; kt++) {
        int k0 = kt * FK;
        const __half* Ks = hs + ((kt & 1) ? OFF_K1 : OFF_K0);

        issueV(kt);
        issueK(kt + 1, kt + 1 < nkt);
        CP_WAIT2();                 // K(kt) done; V(kt), K(kt+1) in flight
        __syncthreads();

        bool active = (k0 <= rowbase + 15);
        if (active) {
            // ---- S = Q K^T : 8 ks steps of k=16 ----
#pragma unroll
            for (int nj = 0; nj < 8; nj++)
#pragma unroll
                for (int r = 0; r < 4; r++) s[nj][r] = 0.f;

#pragma unroll
            for (int ks = 0; ks < 8; ks++) {
                uint32_t a[4];
                a[0] = *(const uint32_t*)(Qs + (rq + g    ) * QSTR + ks*16 + 2*tg);
                a[1] = *(const uint32_t*)(Qs + (rq + g + 8) * QSTR + ks*16 + 2*tg);
                a[2] = *(const uint32_t*)(Qs + (rq + g    ) * QSTR + ks*16 + 8 + 2*tg);
                a[3] = *(const uint32_t*)(Qs + (rq + g + 8) * QSTR + ks*16 + 8 + 2*tg);
#pragma unroll
                for (int nj = 0; nj < 8; nj++) {
                    uint32_t b[2];
                    b[0] = *(const uint32_t*)(Ks + (nj*8 + g) * KSTR + ks*16 + 2*tg);
                    b[1] = *(const uint32_t*)(Ks + (nj*8 + g) * KSTR + ks*16 + 8 + 2*tg);
                    mma_f16(s[nj], a, b);
                }
            }

            // ---- causal mask ----
            if (k0 + FK - 1 > rowbase) {
#pragma unroll
                for (int nj = 0; nj < 8; nj++) {
                    int c = k0 + nj*8 + 2*tg;
                    if (c     > r0g) s[nj][0] = -1e30f;
                    if (c + 1 > r0g) s[nj][1] = -1e30f;
                    if (c     > r1g) s[nj][2] = -1e30f;
                    if (c + 1 > r1g) s[nj][3] = -1e30f;
                }
            }

            // ---- online softmax (warp-local, quad reductions) ----
            float mx0 = -1e30f, mx1 = -1e30f;
#pragma unroll
            for (int nj = 0; nj < 8; nj++) {
                mx0 = fmaxf(mx0, fmaxf(s[nj][0], s[nj][1]));
                mx1 = fmaxf(mx1, fmaxf(s[nj][2], s[nj][3]));
            }
            mx0 = fmaxf(mx0, __shfl_xor_sync(0xffffffff, mx0, 1));
            mx0 = fmaxf(mx0, __shfl_xor_sync(0xffffffff, mx0, 2));
            mx1 = fmaxf(mx1, __shfl_xor_sync(0xffffffff, mx1, 1));
            mx1 = fmaxf(mx1, __shfl_xor_sync(0xffffffff, mx1, 2));

            float mn0 = fmaxf(m0r, mx0);
            float mn1 = fmaxf(m1r, mx1);
            float al0 = __expf((m0r - mn0) * scale);
            float al1 = __expf((m1r - mn1) * scale);
            m0r = mn0; m1r = mn1;

            float sum0 = 0.f, sum1 = 0.f;
#pragma unroll
            for (int nj = 0; nj < 8; nj++) {
                float p0 = __expf((s[nj][0] - mn0) * scale);
                float p1 = __expf((s[nj][1] - mn0) * scale);
                float p2 = __expf((s[nj][2] - mn1) * scale);
                float p3 = __expf((s[nj][3] - mn1) * scale);
                s[nj][0] = p0; s[nj][1] = p1; s[nj][2] = p2; s[nj][3] = p3;
                sum0 += p0 + p1; sum1 += p2 + p3;
            }
            sum0 += __shfl_xor_sync(0xffffffff, sum0, 1);
            sum0 += __shfl_xor_sync(0xffffffff, sum0, 2);
            sum1 += __shfl_xor_sync(0xffffffff, sum1, 1);
            sum1 += __shfl_xor_sync(0xffffffff, sum1, 2);

            l0 = l0 * al0 + sum0;
            l1 = l1 * al1 + sum1;

#pragma unroll
            for (int t2 = 0; t2 < 16; t2++) {
                o[t2][0] *= al0; o[t2][1] *= al0;
                o[t2][2] *= al1; o[t2][3] *= al1;
            }

            // ---- write P (half2 pairs, natural layout) ----
            int pr0 = (rq + g) * PSTR;
            int pr1 = (rq + g + 8) * PSTR;
#pragma unroll
            for (int nj = 0; nj < 8; nj++) {
                int c = nj*8 + 2*tg;
                *(__half2*)(Ps + pr0 + c) = __floats2half2_rn(s[nj][0], s[nj][1]);
                *(__half2*)(Ps + pr1 + c) = __floats2half2_rn(s[nj][2], s[nj][3]);
            }
        }

        CP_WAIT1();                 // V(kt) done; K(kt+1) may be in flight
        __syncthreads();

        if (active) {
            // ---- O += P V : 4 ks2 steps of k=16 tokens, 16 d-tiles ----
            int pr0 = (rq + g) * PSTR;
            int pr1 = (rq + g + 8) * PSTR;
#pragma unroll
            for (int ks2 = 0; ks2 < 4; ks2++) {
                uint32_t a2[4];
                a2[0] = *(const uint32_t*)(Ps + pr0 + ks2*16 + 2*tg);
                a2[1] = *(const uint32_t*)(Ps + pr1 + ks2*16 + 2*tg);
                a2[2] = *(const uint32_t*)(Ps + pr0 + ks2*16 + 8 + 2*tg);
                a2[3] = *(const uint32_t*)(Ps + pr1 + ks2*16 + 8 + 2*tg);
#pragma unroll
                for (int nj2 = 0; nj2 < 16; nj2++) {
                    uint32_t b2[2];
                    b2[0] = *(const uint32_t*)(Vs + (nj2*8 + g) * VSTR + ks2*16 + 2*tg);
                    b2[1] = *(const uint32_t*)(Vs + (nj2*8 + g) * VSTR + ks2*16 + 8 + 2*tg);
                    mma_f16(o[nj2], a2, b2);
                }
            }
        }
        __syncthreads();            // V buffer + K stage free for next iter
    }

    // epilogue: normalize + write att as half (proj GEMM A operand)
    float inv0 = 1.0f / l0;
    float inv1 = 1.0f / l1;
    int b = bh >> 4, h = bh & 15;
#pragma unroll
    for (int nj2 = 0; nj2 < 16; nj2++) {
        int col = h * HD + nj2*8 + 2*tg;
        *(__half2*)(Oatt + (size_t)(b*TSEQ + r0g) * DIM + col) =
            __floats2half2_rn(o[nj2][0] * inv0, o[nj2][1] * inv0);
        *(__half2*)(Oatt + (size_t)(b*TSEQ + r1g) * DIM + col) =
            __floats2half2_rn(o[nj2][2] * inv1, o[nj2][3] * inv1);
    }
}

// ---------------- launch ------------------------------------------------------
extern "C" void kernel_launch(void* const* d_in, const int* in_sizes, int n_in,
                              void* d_out, int out_size) {
    const float* x      = (const float*)d_in[0];
    const float* w_qkv  = (const float*)d_in[1];
    const float* w_proj = (const float*)d_in[2];
    float* out = (float*)d_out;

    float *qkv, *ct, *st;
    __half *xh, *wqkvh, *wprojh, *qh, *kh, *vth, *atth;
    cudaGetSymbolAddress((void**)&qkv,    g_qkv);
    cudaGetSymbolAddress((void**)&ct,     g_ctab);
    cudaGetSymbolAddress((void**)&st,     g_stab);
    cudaGetSymbolAddress((void**)&xh,     g_xh);
    cudaGetSymbolAddress((void**)&wqkvh,  g_wqkvh);
    cudaGetSymbolAddress((void**)&wprojh, g_wprojh);
    cudaGetSymbolAddress((void**)&qh,     g_qh);
    cudaGetSymbolAddress((void**)&kh,     g_kh);
    cudaGetSymbolAddress((void**)&vth,    g_vth);
    cudaGetSymbolAddress((void**)&atth,   g_atth);

    cudaFuncSetAttribute(gemm_h,  cudaFuncAttributeMaxDynamicSharedMemorySize, GEMMH_SMEM);
    cudaFuncSetAttribute(flash_h, cudaFuncAttributeMaxDynamicSharedMemorySize, FLASHH_BYTES);

    build_tab<<<TSEQ, HD>>>(ct, st);

    round_half<<<(M1*(size_t)DIM)/(256*8), 256>>>(x, xh);
    round_half<<<((size_t)N_QKV*DIM)/(256*8), 256>>>(w_qkv, wqkvh);
    round_half<<<((size_t)DIM*DIM)/(256*8), 256>>>(w_proj, wprojh);

    gemm_h<<<dim3(N_QKV/BN, M1/BM), 256, GEMMH_SMEM>>>(xh, wqkvh, qkv, M1, N_QKV, DIM);

    rope_split<<<dim3(NH, M1), HD>>>(qkv, ct, st, qh, kh);
    vtrans<<<dim3(TSEQ/32, HD/32, BATCH*NH), dim3(32, 8)>>>(qkv, vth);

    flash_h<<<dim3(TSEQ/FQ, BATCH*NH), 256, FLASHH_BYTES>>>(qh, kh, vth, atth);

    gemm_h<<<dim3(DIM/BN, M1/BM), 256, GEMMH_SMEM>>>(atth, wprojh, out, M1, DIM, DIM);
}

// round 13
// speedup vs baseline: 2.1514x; 1.0486x over previous
#include <cuda_runtime.h>
#include <cuda_fp16.h>
#include <math.h>
#include <stdint.h>

// Problem constants
#define BATCH 2
#define TSEQ  4096
#define DIM   2048
#define NH    16
#define HD    128
#define M1    (BATCH*TSEQ)      // 8192
#define N_QKV (3*DIM)           // 6144

// ---------------- scratch (static device globals; no allocs allowed) ----------
__device__ float  g_qkv[(size_t)M1 * N_QKV];           // fp32 qkv (GEMM1 out)
__device__ __half g_xh[(size_t)M1 * DIM];
__device__ __half g_wqkvh[(size_t)N_QKV * DIM];
__device__ __half g_wprojh[(size_t)DIM * DIM];
__device__ __half g_qh[(size_t)BATCH*NH*TSEQ*HD];      // [bh][t][d]
__device__ __half g_kh[(size_t)BATCH*NH*TSEQ*HD];      // [bh][t][d]
__device__ __half g_vth[(size_t)BATCH*NH*HD*TSEQ];     // [bh][d][t]  (transposed)
__device__ __half g_atth[(size_t)M1 * DIM];
__device__ float  g_ctab[(size_t)TSEQ * HD];
__device__ float  g_stab[(size_t)TSEQ * HD];

// ---------------- helpers -----------------------------------------------------
__device__ __forceinline__ void mma_f16(float* d, const uint32_t* a, const uint32_t* b) {
    asm volatile(
        "mma.sync.aligned.m16n8k16.row.col.f32.f16.f16.f32 "
        "{%0,%1,%2,%3}, {%4,%5,%6,%7}, {%8,%9}, {%0,%1,%2,%3};"
        : "+f"(d[0]), "+f"(d[1]), "+f"(d[2]), "+f"(d[3])
        : "r"(a[0]), "r"(a[1]), "r"(a[2]), "r"(a[3]), "r"(b[0]), "r"(b[1]));
}

__device__ __forceinline__ void ldsm_x4(uint32_t* r, uint32_t saddr) {
    asm volatile("ldmatrix.sync.aligned.m8n8.x4.shared.b16 {%0,%1,%2,%3}, [%4];"
        : "=r"(r[0]), "=r"(r[1]), "=r"(r[2]), "=r"(r[3]) : "r"(saddr));
}

__device__ __forceinline__ uint32_t smem_u32(const void* p) {
    uint32_t a;
    asm("{ .reg .u64 t; cvta.to.shared.u64 t, %1; cvt.u32.u64 %0, t; }" : "=r"(a) : "l"(p));
    return a;
}
__device__ __forceinline__ void cp_async16(uint32_t saddr, const void* gaddr) {
    asm volatile("cp.async.cg.shared.global [%0], [%1], 16;" :: "r"(saddr), "l"(gaddr));
}
#define CP_COMMIT() asm volatile("cp.async.commit_group;" ::: "memory")
#define CP_WAIT1()  asm volatile("cp.async.wait_group 1;" ::: "memory")
#define CP_WAIT2()  asm volatile("cp.async.wait_group 2;" ::: "memory")

__device__ __forceinline__ uint32_t h2u(__half2 h) {
    union { __half2 h; uint32_t u; } c; c.h = h; return c.u;
}

// ---------------- cos/sin table ----------------------------------------------
__global__ void build_tab(float* __restrict__ ct, float* __restrict__ st) {
    int t = blockIdx.x;
    int j = threadIdx.x;
    int m = j & 63;
    float base = (float)pow(10000.0, (double)m / 64.0);
    float invf = 1.0f / base;
    float ang = (float)t * invf;
    ct[t*HD + j] = cosf(ang);
    st[t*HD + j] = sinf(ang);
}

// ---------------- fp32 -> fp16 pass (8 elems/thread) --------------------------
__global__ void round_half(const float* __restrict__ in, __half* __restrict__ out) {
    size_t i = ((size_t)blockIdx.x * 256 + threadIdx.x) * 8;
    float4 v0 = *(const float4*)(in + i);
    float4 v1 = *(const float4*)(in + i + 4);
    uint4 u;
    u.x = h2u(__floats2half2_rn(v0.x, v0.y));
    u.y = h2u(__floats2half2_rn(v0.z, v0.w));
    u.z = h2u(__floats2half2_rn(v1.x, v1.y));
    u.w = h2u(__floats2half2_rn(v1.z, v1.w));
    *(uint4*)(out + i) = u;
}

// ---------------- fp16 cp.async pipelined GEMM: C = A * B^T -------------------
// A[M,K], B[N,K] half; C[M,N] float. 128x128 tile, BK=32, 3 stages, 8 warps 2x4.
#define BM 128
#define BN 128
#define BKH 32
#define STAGES 3
#define HSTR 40
#define GEMMH_SMEM (STAGES * (BM + BN) * HSTR * 2)    // 61440 B

__global__ __launch_bounds__(256, 2) void gemm_h(
    const __half* __restrict__ A, const __half* __restrict__ B,
    float* __restrict__ C, int M, int N, int K)
{
    extern __shared__ __half hsm[];
    uint32_t sbase = smem_u32(hsm);
    const uint32_t boff = STAGES * BM * HSTR;          // halves

    int tid  = threadIdx.x;
    int wid  = tid >> 5, lane = tid & 31;
    int g    = lane >> 2, tg = lane & 3;
    int wm   = wid >> 2, wn = wid & 3;
    int m0   = blockIdx.y * BM;
    int n0   = blockIdx.x * BN;
    int lrow = tid >> 2;              // 0..63
    int lc8  = (tid & 3) << 3;        // 0,8,16,24 (halves)

    // ldmatrix lane address components
    int la_row = lane & 15;           // A/P row offset
    int la_k   = (lane >> 4) << 3;    // A/P k offset
    int lb_row = ((lane >> 4) << 3) + (lane & 7);   // B row offset
    int lb_k   = ((lane >> 3) & 1) << 3;            // B k offset

    float acc[4][4][4];
#pragma unroll
    for (int i = 0; i < 4; i++)
#pragma unroll
        for (int j = 0; j < 4; j++)
#pragma unroll
            for (int r = 0; r < 4; r++) acc[i][j][r] = 0.f;

    const int nch = K / BKH;

    auto issue = [&](int ch, int s, bool pred) {
        if (pred) {
            const __half* Ag = A + (size_t)m0 * K + ch * BKH;
            const __half* Bg = B + (size_t)n0 * K + ch * BKH;
            uint32_t as = sbase + (uint32_t)(s * BM * HSTR) * 2u;
            uint32_t bs = sbase + (boff + (uint32_t)(s * BN * HSTR)) * 2u;
#pragma unroll
            for (int e = 0; e < 2; e++) {
                int r = lrow + e * 64;
                cp_async16(as + (uint32_t)(r * HSTR + lc8) * 2u, Ag + (size_t)r * K + lc8);
                cp_async16(bs + (uint32_t)(r * HSTR + lc8) * 2u, Bg + (size_t)r * K + lc8);
            }
        }
        CP_COMMIT();
    };

    issue(0, 0, true);
    issue(1, 1, 1 < nch);

    for (int ch = 0; ch < nch; ch++) {
        CP_WAIT1();
        __syncthreads();
        issue(ch + 2, (ch + 2) % STAGES, ch + 2 < nch);

        int s = ch % STAGES;
        uint32_t asad = sbase + (uint32_t)(s * BM * HSTR) * 2u;
        uint32_t bsad = sbase + (boff + (uint32_t)(s * BN * HSTR)) * 2u;

#pragma unroll
        for (int ks = 0; ks < BKH; ks += 16) {
            uint32_t afr[4][4];
#pragma unroll
            for (int mi = 0; mi < 4; mi++) {
                int mr = wm * 64 + mi * 16;
                ldsm_x4(afr[mi], asad + (uint32_t)((mr + la_row) * HSTR + ks + la_k) * 2u);
            }
            uint32_t bfr[4][2];
#pragma unroll
            for (int p = 0; p < 2; p++) {
                int nr2 = wn * 32 + p * 16;
                uint32_t r4[4];
                ldsm_x4(r4, bsad + (uint32_t)((nr2 + lb_row) * HSTR + ks + lb_k) * 2u);
                bfr[2*p  ][0] = r4[0]; bfr[2*p  ][1] = r4[1];
                bfr[2*p+1][0] = r4[2]; bfr[2*p+1][1] = r4[3];
            }
#pragma unroll
            for (int mi = 0; mi < 4; mi++)
#pragma unroll
                for (int nj = 0; nj < 4; nj++)
                    mma_f16(acc[mi][nj], afr[mi], bfr[nj]);
        }
        __syncthreads();
    }

#pragma unroll
    for (int mi = 0; mi < 4; mi++) {
#pragma unroll
        for (int nj = 0; nj < 4; nj++) {
            int row = m0 + wm * 64 + mi * 16 + g;
            int col = n0 + wn * 32 + nj * 8 + tg * 2;
            *(float2*)(C + (size_t)row * N + col) =
                make_float2(acc[mi][nj][0], acc[mi][nj][1]);
            *(float2*)(C + (size_t)(row + 8) * N + col) =
                make_float2(acc[mi][nj][2], acc[mi][nj][3]);
        }
    }
}

// ---------------- RoPE + head split -> half Q,K ------------------------------
__global__ void rope_split(const float* __restrict__ qkv,
                           const float* __restrict__ ct, const float* __restrict__ st,
                           __half* __restrict__ Qo, __half* __restrict__ Ko)
{
    int h  = blockIdx.x;
    int bt = blockIdx.y;
    int j  = threadIdx.x;
    int b  = bt >> 12;
    int t  = bt & (TSEQ - 1);

    size_t base = (size_t)bt * N_QKV + h * HD;
    float c = ct[t*HD + j];
    float s = st[t*HD + j];

    float xq  = qkv[base + j];
    float xqp = qkv[base + (j ^ 1)];
    float rq  = (j & 1) ? xqp : -xqp;

    float xk  = qkv[base + DIM + j];
    float xkp = qkv[base + DIM + (j ^ 1)];
    float rk  = (j & 1) ? xkp : -xkp;

    size_t ob = ((size_t)(b*NH + h) * TSEQ + t) * HD + j;
    Qo[ob] = __float2half(xq * c + rq * s);
    Ko[ob] = __float2half(xk * c + rk * s);
}

// ---------------- V transpose: qkv -> Vt[bh][d][t] (half) --------------------
__global__ void vtrans(const float* __restrict__ qkv, __half* __restrict__ Vt) {
    __shared__ float tile[32][33];
    int bh = blockIdx.z;
    int b  = bh >> 4, h = bh & 15;
    int t0 = blockIdx.x * 32;
    int d0 = blockIdx.y * 32;
    int tx = threadIdx.x, ty = threadIdx.y;   // 32 x 8

#pragma unroll
    for (int i = 0; i < 4; i++) {
        int t = t0 + ty + i * 8;
        tile[ty + i*8][tx] = qkv[(size_t)(b*TSEQ + t) * N_QKV + 2*DIM + h*HD + d0 + tx];
    }
    __syncthreads();
#pragma unroll
    for (int i = 0; i < 4; i++) {
        int d = d0 + ty + i * 8;
        Vt[((size_t)bh * HD + d) * TSEQ + t0 + tx] = __float2half(tile[tx][ty + i*8]);
    }
}

// ---------------- fp16 mma flash attention (causal, cp.async pipelined) ------
// Q tile 128, K tile 64, 8 warps; warp = 16 Q rows x full K width.
#define FQ 128
#define FK 64
#define QSTR 136       // halves
#define KSTR 136
#define VSTR 72
#define PSTR 72
#define OFF_Q  0
#define OFF_K0 (OFF_Q  + FQ*QSTR)     // 17408
#define OFF_K1 (OFF_K0 + FK*KSTR)     // 26112
#define OFF_V  (OFF_K1 + FK*KSTR)     // 34816
#define OFF_P  (OFF_V  + HD*VSTR)     // 44032
#define FLASHH_HALVES (OFF_P + FQ*PSTR)   // 53248
#define FLASHH_BYTES (FLASHH_HALVES * 2)  // 106496

__global__ __launch_bounds__(256, 1) void flash_h(
    const __half* __restrict__ Q, const __half* __restrict__ K,
    const __half* __restrict__ Vt, __half* __restrict__ Oatt)
{
    extern __shared__ __half hs[];
    __half* Ps = hs + OFF_P;
    uint32_t sbase = smem_u32(hs);

    int qi  = blockIdx.x;
    int bh  = blockIdx.y;
    int tid = threadIdx.x;
    int w    = tid >> 5;
    int lane = tid & 31;
    int g    = lane >> 2;
    int tg   = lane & 3;

    int la_row = lane & 15;
    int la_k   = (lane >> 4) << 3;
    int lb_row = ((lane >> 4) << 3) + (lane & 7);
    int lb_k   = ((lane >> 3) & 1) << 3;

    const __half* Qp  = Q  + (size_t)bh * TSEQ * HD;
    const __half* Kp  = K  + (size_t)bh * TSEQ * HD;
    const __half* Vtp = Vt + (size_t)bh * HD * TSEQ;

    int q0 = qi * FQ;
    int nkt = 2 * qi + 2;

    auto issueK = [&](int kt, bool pred) {
        if (pred) {
            int k0 = kt * FK;
            uint32_t kb = sbase + (uint32_t)((kt & 1) ? OFF_K1 : OFF_K0) * 2u;
#pragma unroll
            for (int e = 0; e < 4; e++) {
                int idx = tid + e * 256;
                int r  = idx >> 4;
                int c8 = (idx & 15) << 3;
                cp_async16(kb + (uint32_t)(r * KSTR + c8) * 2u,
                           Kp + (size_t)(k0 + r) * HD + c8);
            }
        }
        CP_COMMIT();
    };
    auto issueV = [&](int kt) {
        int k0 = kt * FK;
        uint32_t vb = sbase + (uint32_t)OFF_V * 2u;
#pragma unroll
        for (int e = 0; e < 4; e++) {
            int idx = tid + e * 256;
            int d  = idx >> 3;
            int c8 = (idx & 7) << 3;
            cp_async16(vb + (uint32_t)(d * VSTR + c8) * 2u,
                       Vtp + (size_t)d * TSEQ + k0 + c8);
        }
        CP_COMMIT();
    };

    issueK(0, true);

    // load Q tile
#pragma unroll
    for (int e = 0; e < 8; e++) {
        int idx = tid + e * 256;
        int r  = idx >> 4;
        int c8 = (idx & 15) << 3;
        uint4 v = *(const uint4*)(Qp + (size_t)(q0 + r) * HD + c8);
        *(uint4*)(hs + OFF_Q + r * QSTR + c8) = v;
    }

    float o[16][4];
#pragma unroll
    for (int i = 0; i < 16; i++)
#pragma unroll
        for (int j = 0; j < 4; j++) o[i][j] = 0.f;

    float m0r = -1e30f, m1r = -1e30f;
    float l0 = 0.f, l1 = 0.f;
    const float scale = 0.08838834764831845f;   // 1/sqrt(128)

    int rowbase = q0 + w * 16;
    int r0g = rowbase + g;
    int r1g = rowbase + g + 8;
    int rq = rowbase - q0;

    uint32_t qad = sbase + (uint32_t)(OFF_Q + (rq + la_row) * QSTR + la_k) * 2u;
    uint32_t pad_a = sbase + (uint32_t)(OFF_P + (rq + la_row) * PSTR + la_k) * 2u;

    float s[8][4];

    for (int kt = 0; kt < nkt; kt++) {
        int k0 = kt * FK;
        uint32_t kad = sbase + (uint32_t)(((kt & 1) ? OFF_K1 : OFF_K0) + lb_row * KSTR + lb_k) * 2u;

        issueV(kt);
        issueK(kt + 1, kt + 1 < nkt);
        CP_WAIT2();                 // K(kt) done; V(kt), K(kt+1) in flight
        __syncthreads();

        bool active = (k0 <= rowbase + 15);
        if (active) {
            // ---- S = Q K^T : 8 ks steps of k=16 ----
#pragma unroll
            for (int nj = 0; nj < 8; nj++)
#pragma unroll
                for (int r = 0; r < 4; r++) s[nj][r] = 0.f;

#pragma unroll
            for (int ks = 0; ks < 8; ks++) {
                uint32_t a[4];
                ldsm_x4(a, qad + (uint32_t)(ks * 16) * 2u);
                uint32_t bfr[8][2];
#pragma unroll
                for (int p = 0; p < 4; p++) {
                    uint32_t r4[4];
                    ldsm_x4(r4, kad + (uint32_t)(p * 16 * KSTR + ks * 16) * 2u);
                    bfr[2*p  ][0] = r4[0]; bfr[2*p  ][1] = r4[1];
                    bfr[2*p+1][0] = r4[2]; bfr[2*p+1][1] = r4[3];
                }
#pragma unroll
                for (int nj = 0; nj < 8; nj++)
                    mma_f16(s[nj], a, bfr[nj]);
            }

            // ---- causal mask ----
            if (k0 + FK - 1 > rowbase) {
#pragma unroll
                for (int nj = 0; nj < 8; nj++) {
                    int c = k0 + nj*8 + 2*tg;
                    if (c     > r0g) s[nj][0] = -1e30f;
                    if (c + 1 > r0g) s[nj][1] = -1e30f;
                    if (c     > r1g) s[nj][2] = -1e30f;
                    if (c + 1 > r1g) s[nj][3] = -1e30f;
                }
            }

            // ---- online softmax (warp-local, quad reductions) ----
            float mx0 = -1e30f, mx1 = -1e30f;
#pragma unroll
            for (int nj = 0; nj < 8; nj++) {
                mx0 = fmaxf(mx0, fmaxf(s[nj][0], s[nj][1]));
                mx1 = fmaxf(mx1, fmaxf(s[nj][2], s[nj][3]));
            }
            mx0 = fmaxf(mx0, __shfl_xor_sync(0xffffffff, mx0, 1));
            mx0 = fmaxf(mx0, __shfl_xor_sync(0xffffffff, mx0, 2));
            mx1 = fmaxf(mx1, __shfl_xor_sync(0xffffffff, mx1, 1));
            mx1 = fmaxf(mx1, __shfl_xor_sync(0xffffffff, mx1, 2));

            float mn0 = fmaxf(m0r, mx0);
            float mn1 = fmaxf(m1r, mx1);
            float al0 = __expf((m0r - mn0) * scale);
            float al1 = __expf((m1r - mn1) * scale);
            m0r = mn0; m1r = mn1;

            float sum0 = 0.f, sum1 = 0.f;
#pragma unroll
            for (int nj = 0; nj < 8; nj++) {
                float p0 = __expf((s[nj][0] - mn0) * scale);
                float p1 = __expf((s[nj][1] - mn0) * scale);
                float p2 = __expf((s[nj][2] - mn1) * scale);
                float p3 = __expf((s[nj][3] - mn1) * scale);
                s[nj][0] = p0; s[nj][1] = p1; s[nj][2] = p2; s[nj][3] = p3;
                sum0 += p0 + p1; sum1 += p2 + p3;
            }
            sum0 += __shfl_xor_sync(0xffffffff, sum0, 1);
            sum0 += __shfl_xor_sync(0xffffffff, sum0, 2);
            sum1 += __shfl_xor_sync(0xffffffff, sum1, 1);
            sum1 += __shfl_xor_sync(0xffffffff, sum1, 2);

            l0 = l0 * al0 + sum0;
            l1 = l1 * al1 + sum1;

#pragma unroll
            for (int t2 = 0; t2 < 16; t2++) {
                o[t2][0] *= al0; o[t2][1] *= al0;
                o[t2][2] *= al1; o[t2][3] *= al1;
            }

            // ---- write P (half2 pairs, natural layout) ----
            int pr0 = (rq + g) * PSTR;
            int pr1 = (rq + g + 8) * PSTR;
#pragma unroll
            for (int nj = 0; nj < 8; nj++) {
                int c = nj*8 + 2*tg;
                *(__half2*)(Ps + pr0 + c) = __floats2half2_rn(s[nj][0], s[nj][1]);
                *(__half2*)(Ps + pr1 + c) = __floats2half2_rn(s[nj][2], s[nj][3]);
            }
        }

        CP_WAIT1();                 // V(kt) done; K(kt+1) may be in flight
        __syncthreads();

        if (active) {
            // ---- O += P V : 4 ks2 steps of k=16 tokens, 16 d-tiles ----
            uint32_t vad = sbase + (uint32_t)(OFF_V + lb_row * VSTR + lb_k) * 2u;
#pragma unroll
            for (int ks2 = 0; ks2 < 4; ks2++) {
                uint32_t a2[4];
                ldsm_x4(a2, pad_a + (uint32_t)(ks2 * 16) * 2u);
#pragma unroll
                for (int p = 0; p < 8; p++) {
                    uint32_t r4[4];
                    ldsm_x4(r4, vad + (uint32_t)(p * 16 * VSTR + ks2 * 16) * 2u);
                    uint32_t b0[2] = { r4[0], r4[1] };
                    uint32_t b1[2] = { r4[2], r4[3] };
                    mma_f16(o[2*p  ], a2, b0);
                    mma_f16(o[2*p+1], a2, b1);
                }
            }
        }
        __syncthreads();            // V buffer + K stage free for next iter
    }

    // epilogue: normalize + write att as half (proj GEMM A operand)
    float inv0 = 1.0f / l0;
    float inv1 = 1.0f / l1;
    int b = bh >> 4, h = bh & 15;
#pragma unroll
    for (int nj2 = 0; nj2 < 16; nj2++) {
        int col = h * HD + nj2*8 + 2*tg;
        *(__half2*)(Oatt + (size_t)(b*TSEQ + r0g) * DIM + col) =
            __floats2half2_rn(o[nj2][0] * inv0, o[nj2][1] * inv0);
        *(__half2*)(Oatt + (size_t)(b*TSEQ + r1g) * DIM + col) =
            __floats2half2_rn(o[nj2][2] * inv1, o[nj2][3] * inv1);
    }
}

// ---------------- launch ------------------------------------------------------
extern "C" void kernel_launch(void* const* d_in, const int* in_sizes, int n_in,
                              void* d_out, int out_size) {
    const float* x      = (const float*)d_in[0];
    const float* w_qkv  = (const float*)d_in[1];
    const float* w_proj = (const float*)d_in[2];
    float* out = (float*)d_out;

    float *qkv, *ct, *st;
    __half *xh, *wqkvh, *wprojh, *qh, *kh, *vth, *atth;
    cudaGetSymbolAddress((void**)&qkv,    g_qkv);
    cudaGetSymbolAddress((void**)&ct,     g_ctab);
    cudaGetSymbolAddress((void**)&st,     g_stab);
    cudaGetSymbolAddress((void**)&xh,     g_xh);
    cudaGetSymbolAddress((void**)&wqkvh,  g_wqkvh);
    cudaGetSymbolAddress((void**)&wprojh, g_wprojh);
    cudaGetSymbolAddress((void**)&qh,     g_qh);
    cudaGetSymbolAddress((void**)&kh,     g_kh);
    cudaGetSymbolAddress((void**)&vth,    g_vth);
    cudaGetSymbolAddress((void**)&atth,   g_atth);

    cudaFuncSetAttribute(gemm_h,  cudaFuncAttributeMaxDynamicSharedMemorySize, GEMMH_SMEM);
    cudaFuncSetAttribute(flash_h, cudaFuncAttributeMaxDynamicSharedMemorySize, FLASHH_BYTES);

    build_tab<<<TSEQ, HD>>>(ct, st);

    round_half<<<(M1*(size_t)DIM)/(256*8), 256>>>(x, xh);
    round_half<<<((size_t)N_QKV*DIM)/(256*8), 256>>>(w_qkv, wqkvh);
    round_half<<<((size_t)DIM*DIM)/(256*8), 256>>>(w_proj, wprojh);

    gemm_h<<<dim3(N_QKV/BN, M1/BM), 256, GEMMH_SMEM>>>(xh, wqkvh, qkv, M1, N_QKV, DIM);

    rope_split<<<dim3(NH, M1), HD>>>(qkv, ct, st, qh, kh);
    vtrans<<<dim3(TSEQ/32, HD/32, BATCH*NH), dim3(32, 8)>>>(qkv, vth);

    flash_h<<<dim3(TSEQ/FQ, BATCH*NH), 256, FLASHH_BYTES>>>(qh, kh, vth, atth);

    gemm_h<<<dim3(DIM/BN, M1/BM), 256, GEMMH_SMEM>>>(atth, wprojh, out, M1, DIM, DIM);
}

// round 14
// speedup vs baseline: 2.3897x; 1.1108x over previous
#include <cuda_runtime.h>
#include <cuda_fp16.h>
#include <math.h>
#include <stdint.h>

// Problem constants
#define BATCH 2
#define TSEQ  4096
#define DIM   2048
#define NH    16
#define HD    128
#define M1    (BATCH*TSEQ)      // 8192
#define N_QKV (3*DIM)           // 6144

// ---------------- scratch (static device globals; no allocs allowed) ----------
__device__ float  g_qkv[(size_t)M1 * N_QKV];           // fp32 qkv (GEMM1 out)
__device__ __half g_xh[(size_t)M1 * DIM];
__device__ __half g_wqkvh[(size_t)N_QKV * DIM];
__device__ __half g_wprojh[(size_t)DIM * DIM];
__device__ __half g_qh[(size_t)BATCH*NH*TSEQ*HD];      // [bh][t][d]
__device__ __half g_kh[(size_t)BATCH*NH*TSEQ*HD];      // [bh][t][d]
__device__ __half g_vth[(size_t)BATCH*NH*HD*TSEQ];     // [bh][d][t]  (transposed)
__device__ __half g_atth[(size_t)M1 * DIM];
__device__ float  g_ctab[(size_t)TSEQ * HD];
__device__ float  g_stab[(size_t)TSEQ * HD];

// ---------------- helpers -----------------------------------------------------
__device__ __forceinline__ void mma_f16(float* d, const uint32_t* a, const uint32_t* b) {
    asm volatile(
        "mma.sync.aligned.m16n8k16.row.col.f32.f16.f16.f32 "
        "{%0,%1,%2,%3}, {%4,%5,%6,%7}, {%8,%9}, {%0,%1,%2,%3};"
        : "+f"(d[0]), "+f"(d[1]), "+f"(d[2]), "+f"(d[3])
        : "r"(a[0]), "r"(a[1]), "r"(a[2]), "r"(a[3]), "r"(b[0]), "r"(b[1]));
}

__device__ __forceinline__ void ldsm_x4(uint32_t* r, uint32_t saddr) {
    asm volatile("ldmatrix.sync.aligned.m8n8.x4.shared.b16 {%0,%1,%2,%3}, [%4];"
        : "=r"(r[0]), "=r"(r[1]), "=r"(r[2]), "=r"(r[3]) : "r"(saddr));
}

__device__ __forceinline__ uint32_t smem_u32(const void* p) {
    uint32_t a;
    asm("{ .reg .u64 t; cvta.to.shared.u64 t, %1; cvt.u32.u64 %0, t; }" : "=r"(a) : "l"(p));
    return a;
}
__device__ __forceinline__ void cp_async16(uint32_t saddr, const void* gaddr) {
    asm volatile("cp.async.cg.shared.global [%0], [%1], 16;" :: "r"(saddr), "l"(gaddr));
}
#define CP_COMMIT() asm volatile("cp.async.commit_group;" ::: "memory")
#define CP_WAIT1()  asm volatile("cp.async.wait_group 1;" ::: "memory")
#define CP_WAIT2()  asm volatile("cp.async.wait_group 2;" ::: "memory")

__device__ __forceinline__ uint32_t h2u(__half2 h) {
    union { __half2 h; uint32_t u; } c; c.h = h; return c.u;
}

// ---------------- cos/sin table ----------------------------------------------
__global__ void build_tab(float* __restrict__ ct, float* __restrict__ st) {
    int t = blockIdx.x;
    int j = threadIdx.x;
    int m = j & 63;
    float base = (float)pow(10000.0, (double)m / 64.0);
    float invf = 1.0f / base;
    float ang = (float)t * invf;
    ct[t*HD + j] = cosf(ang);
    st[t*HD + j] = sinf(ang);
}

// ---------------- fp32 -> fp16 pass (8 elems/thread) --------------------------
__global__ void round_half(const float* __restrict__ in, __half* __restrict__ out) {
    size_t i = ((size_t)blockIdx.x * 256 + threadIdx.x) * 8;
    float4 v0 = *(const float4*)(in + i);
    float4 v1 = *(const float4*)(in + i + 4);
    uint4 u;
    u.x = h2u(__floats2half2_rn(v0.x, v0.y));
    u.y = h2u(__floats2half2_rn(v0.z, v0.w));
    u.z = h2u(__floats2half2_rn(v1.x, v1.y));
    u.w = h2u(__floats2half2_rn(v1.z, v1.w));
    *(uint4*)(out + i) = u;
}

// ---------------- fp16 cp.async pipelined GEMM: C = A * B^T -------------------
// 128x128 CTA tile, 4 warps (2x2) of 64x64, BK=32, 4 stages, 128 threads.
#define BM 128
#define BN 128
#define BKH 32
#define STAGES 4
#define HSTR 40
#define GEMMH_SMEM (STAGES * (BM + BN) * HSTR * 2)    // 81920 B

__global__ __launch_bounds__(128, 2) void gemm_h(
    const __half* __restrict__ A, const __half* __restrict__ B,
    float* __restrict__ C, int M, int N, int K)
{
    extern __shared__ __half hsm[];
    uint32_t sbase = smem_u32(hsm);
    const uint32_t boff = STAGES * BM * HSTR;          // halves

    int tid  = threadIdx.x;
    int wid  = tid >> 5, lane = tid & 31;
    int g    = lane >> 2, tg = lane & 3;
    int wm   = wid >> 1, wn = wid & 1;
    int m0   = blockIdx.y * BM;
    int n0   = blockIdx.x * BN;

    // ldmatrix lane address components
    int la_row = lane & 15;
    int la_k   = (lane >> 4) << 3;
    int lb_row = ((lane >> 4) << 3) + (lane & 7);
    int lb_k   = ((lane >> 3) & 1) << 3;

    float acc[4][8][4];
#pragma unroll
    for (int i = 0; i < 4; i++)
#pragma unroll
        for (int j = 0; j < 8; j++)
#pragma unroll
            for (int r = 0; r < 4; r++) acc[i][j][r] = 0.f;

    const int nch = K / BKH;

    auto issue = [&](int ch, bool pred) {
        if (pred) {
            int s = ch % STAGES;
            const __half* Ag = A + (size_t)m0 * K + ch * BKH;
            const __half* Bg = B + (size_t)n0 * K + ch * BKH;
            uint32_t as = sbase + (uint32_t)(s * BM * HSTR) * 2u;
            uint32_t bs = sbase + (boff + (uint32_t)(s * BN * HSTR)) * 2u;
#pragma unroll
            for (int e = 0; e < 4; e++) {
                int idx = tid + e * 128;      // 0..511
                int r  = idx >> 2;            // 0..127
                int c8 = (idx & 3) << 3;      // 0,8,16,24
                cp_async16(as + (uint32_t)(r * HSTR + c8) * 2u, Ag + (size_t)r * K + c8);
                cp_async16(bs + (uint32_t)(r * HSTR + c8) * 2u, Bg + (size_t)r * K + c8);
            }
        }
        CP_COMMIT();
    };

    issue(0, true);
    issue(1, 1 < nch);
    issue(2, 2 < nch);

    for (int ch = 0; ch < nch; ch++) {
        CP_WAIT2();
        __syncthreads();                       // stage ch ready; prior compute drained
        issue(ch + 3, ch + 3 < nch);

        int s = ch % STAGES;
        uint32_t asad = sbase + (uint32_t)(s * BM * HSTR) * 2u;
        uint32_t bsad = sbase + (boff + (uint32_t)(s * BN * HSTR)) * 2u;

#pragma unroll
        for (int ks = 0; ks < BKH; ks += 16) {
            uint32_t afr[4][4];
#pragma unroll
            for (int mi = 0; mi < 4; mi++) {
                int mr = wm * 64 + mi * 16;
                ldsm_x4(afr[mi], asad + (uint32_t)((mr + la_row) * HSTR + ks + la_k) * 2u);
            }
            uint32_t bfr[8][2];
#pragma unroll
            for (int p = 0; p < 4; p++) {
                int nr2 = wn * 64 + p * 16;
                uint32_t r4[4];
                ldsm_x4(r4, bsad + (uint32_t)((nr2 + lb_row) * HSTR + ks + lb_k) * 2u);
                bfr[2*p  ][0] = r4[0]; bfr[2*p  ][1] = r4[1];
                bfr[2*p+1][0] = r4[2]; bfr[2*p+1][1] = r4[3];
            }
#pragma unroll
            for (int mi = 0; mi < 4; mi++)
#pragma unroll
                for (int nj = 0; nj < 8; nj++)
                    mma_f16(acc[mi][nj], afr[mi], bfr[nj]);
        }
    }

#pragma unroll
    for (int mi = 0; mi < 4; mi++) {
#pragma unroll
        for (int nj = 0; nj < 8; nj++) {
            int row = m0 + wm * 64 + mi * 16 + g;
            int col = n0 + wn * 64 + nj * 8 + tg * 2;
            *(float2*)(C + (size_t)row * N + col) =
                make_float2(acc[mi][nj][0], acc[mi][nj][1]);
            *(float2*)(C + (size_t)(row + 8) * N + col) =
                make_float2(acc[mi][nj][2], acc[mi][nj][3]);
        }
    }
}

// ---------------- RoPE + head split -> half Q,K (vectorized) -----------------
// One block per token; c/s loaded once, reused over 4 heads per thread.
__global__ void rope_split(const float* __restrict__ qkv,
                           const float* __restrict__ ct, const float* __restrict__ st,
                           __half* __restrict__ Qo, __half* __restrict__ Ko)
{
    int bt  = blockIdx.x;
    int tid = threadIdx.x;           // 256
    int j2  = tid & 63;              // pair index
    int hh  = tid >> 6;              // 0..3
    int b   = bt >> 12;
    int t   = bt & (TSEQ - 1);
    int j   = 2 * j2;

    float2 c = *(const float2*)(ct + t*HD + j);
    float2 s = *(const float2*)(st + t*HD + j);

#pragma unroll
    for (int e = 0; e < 4; e++) {
        int h = hh + e * 4;
        size_t base = (size_t)bt * N_QKV + h * HD + j;
        float2 xq = *(const float2*)(qkv + base);
        float2 xk = *(const float2*)(qkv + base + DIM);
        float oq0 = xq.x * c.x - xq.y * s.x;
        float oq1 = xq.y * c.y + xq.x * s.y;
        float ok0 = xk.x * c.x - xk.y * s.x;
        float ok1 = xk.y * c.y + xk.x * s.y;
        size_t ob = ((size_t)(b*NH + h) * TSEQ + t) * HD + j;
        *(__half2*)(Qo + ob) = __floats2half2_rn(oq0, oq1);
        *(__half2*)(Ko + ob) = __floats2half2_rn(ok0, ok1);
    }
}

// ---------------- V transpose: qkv -> Vt[bh][d][t] (half) --------------------
__global__ void vtrans(const float* __restrict__ qkv, __half* __restrict__ Vt) {
    __shared__ float tile[32][33];
    int bh = blockIdx.z;
    int b  = bh >> 4, h = bh & 15;
    int t0 = blockIdx.x * 32;
    int d0 = blockIdx.y * 32;
    int tx = threadIdx.x, ty = threadIdx.y;   // 32 x 8

#pragma unroll
    for (int i = 0; i < 4; i++) {
        int t = t0 + ty + i * 8;
        tile[ty + i*8][tx] = qkv[(size_t)(b*TSEQ + t) * N_QKV + 2*DIM + h*HD + d0 + tx];
    }
    __syncthreads();
#pragma unroll
    for (int i = 0; i < 4; i++) {
        int d = d0 + ty + i * 8;
        Vt[((size_t)bh * HD + d) * TSEQ + t0 + tx] = __float2half(tile[tx][ty + i*8]);
    }
}

// ---------------- fp16 mma flash attention (causal, cp.async pipelined) ------
// Q tile 128, K tile 64, 8 warps; warp = 16 Q rows x full K width.
#define FQ 128
#define FK 64
#define QSTR 136       // halves
#define KSTR 136
#define VSTR 72
#define PSTR 72
#define OFF_Q  0
#define OFF_K0 (OFF_Q  + FQ*QSTR)     // 17408
#define OFF_K1 (OFF_K0 + FK*KSTR)     // 26112
#define OFF_V  (OFF_K1 + FK*KSTR)     // 34816
#define OFF_P  (OFF_V  + HD*VSTR)     // 44032
#define FLASHH_HALVES (OFF_P + FQ*PSTR)   // 53248
#define FLASHH_BYTES (FLASHH_HALVES * 2)  // 106496

__global__ __launch_bounds__(256, 1) void flash_h(
    const __half* __restrict__ Q, const __half* __restrict__ K,
    const __half* __restrict__ Vt, __half* __restrict__ Oatt)
{
    extern __shared__ __half hs[];
    __half* Ps = hs + OFF_P;
    uint32_t sbase = smem_u32(hs);

    int qi  = blockIdx.x;
    int bh  = blockIdx.y;
    int tid = threadIdx.x;
    int w    = tid >> 5;
    int lane = tid & 31;
    int g    = lane >> 2;
    int tg   = lane & 3;

    int la_row = lane & 15;
    int la_k   = (lane >> 4) << 3;
    int lb_row = ((lane >> 4) << 3) + (lane & 7);
    int lb_k   = ((lane >> 3) & 1) << 3;

    const __half* Qp  = Q  + (size_t)bh * TSEQ * HD;
    const __half* Kp  = K  + (size_t)bh * TSEQ * HD;
    const __half* Vtp = Vt + (size_t)bh * HD * TSEQ;

    int q0 = qi * FQ;
    int nkt = 2 * qi + 2;

    auto issueK = [&](int kt, bool pred) {
        if (pred) {
            int k0 = kt * FK;
            uint32_t kb = sbase + (uint32_t)((kt & 1) ? OFF_K1 : OFF_K0) * 2u;
#pragma unroll
            for (int e = 0; e < 4; e++) {
                int idx = tid + e * 256;
                int r  = idx >> 4;
                int c8 = (idx & 15) << 3;
                cp_async16(kb + (uint32_t)(r * KSTR + c8) * 2u,
                           Kp + (size_t)(k0 + r) * HD + c8);
            }
        }
        CP_COMMIT();
    };
    auto issueV = [&](int kt) {
        int k0 = kt * FK;
        uint32_t vb = sbase + (uint32_t)OFF_V * 2u;
#pragma unroll
        for (int e = 0; e < 4; e++) {
            int idx = tid + e * 256;
            int d  = idx >> 3;
            int c8 = (idx & 7) << 3;
            cp_async16(vb + (uint32_t)(d * VSTR + c8) * 2u,
                       Vtp + (size_t)d * TSEQ + k0 + c8);
        }
        CP_COMMIT();
    };

    issueK(0, true);

    // load Q tile
#pragma unroll
    for (int e = 0; e < 8; e++) {
        int idx = tid + e * 256;
        int r  = idx >> 4;
        int c8 = (idx & 15) << 3;
        uint4 v = *(const uint4*)(Qp + (size_t)(q0 + r) * HD + c8);
        *(uint4*)(hs + OFF_Q + r * QSTR + c8) = v;
    }

    float o[16][4];
#pragma unroll
    for (int i = 0; i < 16; i++)
#pragma unroll
        for (int j = 0; j < 4; j++) o[i][j] = 0.f;

    float m0r = -1e30f, m1r = -1e30f;
    float l0 = 0.f, l1 = 0.f;
    const float scale = 0.08838834764831845f;   // 1/sqrt(128)

    int rowbase = q0 + w * 16;
    int r0g = rowbase + g;
    int r1g = rowbase + g + 8;
    int rq = rowbase - q0;

    uint32_t qad = sbase + (uint32_t)(OFF_Q + (rq + la_row) * QSTR + la_k) * 2u;
    uint32_t pad_a = sbase + (uint32_t)(OFF_P + (rq + la_row) * PSTR + la_k) * 2u;

    float s[8][4];

    for (int kt = 0; kt < nkt; kt++) {
        int k0 = kt * FK;
        uint32_t kad = sbase + (uint32_t)(((kt & 1) ? OFF_K1 : OFF_K0) + lb_row * KSTR + lb_k) * 2u;

        issueV(kt);
        issueK(kt + 1, kt + 1 < nkt);
        CP_WAIT2();                 // K(kt) done; V(kt), K(kt+1) in flight
        __syncthreads();

        bool active = (k0 <= rowbase + 15);
        if (active) {
            // ---- S = Q K^T : 8 ks steps of k=16 ----
#pragma unroll
            for (int nj = 0; nj < 8; nj++)
#pragma unroll
                for (int r = 0; r < 4; r++) s[nj][r] = 0.f;

#pragma unroll
            for (int ks = 0; ks < 8; ks++) {
                uint32_t a[4];
                ldsm_x4(a, qad + (uint32_t)(ks * 16) * 2u);
                uint32_t bfr[8][2];
#pragma unroll
                for (int p = 0; p < 4; p++) {
                    uint32_t r4[4];
                    ldsm_x4(r4, kad + (uint32_t)(p * 16 * KSTR + ks * 16) * 2u);
                    bfr[2*p  ][0] = r4[0]; bfr[2*p  ][1] = r4[1];
                    bfr[2*p+1][0] = r4[2]; bfr[2*p+1][1] = r4[3];
                }
#pragma unroll
                for (int nj = 0; nj < 8; nj++)
                    mma_f16(s[nj], a, bfr[nj]);
            }

            // ---- causal mask ----
            if (k0 + FK - 1 > rowbase) {
#pragma unroll
                for (int nj = 0; nj < 8; nj++) {
                    int c = k0 + nj*8 + 2*tg;
                    if (c     > r0g) s[nj][0] = -1e30f;
                    if (c + 1 > r0g) s[nj][1] = -1e30f;
                    if (c     > r1g) s[nj][2] = -1e30f;
                    if (c + 1 > r1g) s[nj][3] = -1e30f;
                }
            }

            // ---- online softmax (warp-local, quad reductions) ----
            float mx0 = -1e30f, mx1 = -1e30f;
#pragma unroll
            for (int nj = 0; nj < 8; nj++) {
                mx0 = fmaxf(mx0, fmaxf(s[nj][0], s[nj][1]));
                mx1 = fmaxf(mx1, fmaxf(s[nj][2], s[nj][3]));
            }
            mx0 = fmaxf(mx0, __shfl_xor_sync(0xffffffff, mx0, 1));
            mx0 = fmaxf(mx0, __shfl_xor_sync(0xffffffff, mx0, 2));
            mx1 = fmaxf(mx1, __shfl_xor_sync(0xffffffff, mx1, 1));
            mx1 = fmaxf(mx1, __shfl_xor_sync(0xffffffff, mx1, 2));

            float mn0 = fmaxf(m0r, mx0);
            float mn1 = fmaxf(m1r, mx1);
            float al0 = __expf((m0r - mn0) * scale);
            float al1 = __expf((m1r - mn1) * scale);
            m0r = mn0; m1r = mn1;

            float sum0 = 0.f, sum1 = 0.f;
#pragma unroll
            for (int nj = 0; nj < 8; nj++) {
                float p0 = __expf((s[nj][0] - mn0) * scale);
                float p1 = __expf((s[nj][1] - mn0) * scale);
                float p2 = __expf((s[nj][2] - mn1) * scale);
                float p3 = __expf((s[nj][3] - mn1) * scale);
                s[nj][0] = p0; s[nj][1] = p1; s[nj][2] = p2; s[nj][3] = p3;
                sum0 += p0 + p1; sum1 += p2 + p3;
            }
            sum0 += __shfl_xor_sync(0xffffffff, sum0, 1);
            sum0 += __shfl_xor_sync(0xffffffff, sum0, 2);
            sum1 += __shfl_xor_sync(0xffffffff, sum1, 1);
            sum1 += __shfl_xor_sync(0xffffffff, sum1, 2);

            l0 = l0 * al0 + sum0;
            l1 = l1 * al1 + sum1;

#pragma unroll
            for (int t2 = 0; t2 < 16; t2++) {
                o[t2][0] *= al0; o[t2][1] *= al0;
                o[t2][2] *= al1; o[t2][3] *= al1;
            }

            // ---- write P (half2 pairs, natural layout) ----
            int pr0 = (rq + g) * PSTR;
            int pr1 = (rq + g + 8) * PSTR;
#pragma unroll
            for (int nj = 0; nj < 8; nj++) {
                int c = nj*8 + 2*tg;
                *(__half2*)(Ps + pr0 + c) = __floats2half2_rn(s[nj][0], s[nj][1]);
                *(__half2*)(Ps + pr1 + c) = __floats2half2_rn(s[nj][2], s[nj][3]);
            }
        }

        CP_WAIT1();                 // V(kt) done; K(kt+1) may be in flight
        __syncthreads();

        if (active) {
            // ---- O += P V : 4 ks2 steps of k=16 tokens, 16 d-tiles ----
            uint32_t vad = sbase + (uint32_t)(OFF_V + lb_row * VSTR + lb_k) * 2u;
#pragma unroll
            for (int ks2 = 0; ks2 < 4; ks2++) {
                uint32_t a2[4];
                ldsm_x4(a2, pad_a + (uint32_t)(ks2 * 16) * 2u);
#pragma unroll
                for (int p = 0; p < 8; p++) {
                    uint32_t r4[4];
                    ldsm_x4(r4, vad + (uint32_t)(p * 16 * VSTR + ks2 * 16) * 2u);
                    uint32_t b0[2] = { r4[0], r4[1] };
                    uint32_t b1[2] = { r4[2], r4[3] };
                    mma_f16(o[2*p  ], a2, b0);
                    mma_f16(o[2*p+1], a2, b1);
                }
            }
        }
        __syncthreads();            // V buffer + K stage free for next iter
    }

    // epilogue: normalize + write att as half (proj GEMM A operand)
    float inv0 = 1.0f / l0;
    float inv1 = 1.0f / l1;
    int b = bh >> 4, h = bh & 15;
#pragma unroll
    for (int nj2 = 0; nj2 < 16; nj2++) {
        int col = h * HD + nj2*8 + 2*tg;
        *(__half2*)(Oatt + (size_t)(b*TSEQ + r0g) * DIM + col) =
            __floats2half2_rn(o[nj2][0] * inv0, o[nj2][1] * inv0);
        *(__half2*)(Oatt + (size_t)(b*TSEQ + r1g) * DIM + col) =
            __floats2half2_rn(o[nj2][2] * inv1, o[nj2][3] * inv1);
    }
}

// ---------------- launch ------------------------------------------------------
extern "C" void kernel_launch(void* const* d_in, const int* in_sizes, int n_in,
                              void* d_out, int out_size) {
    const float* x      = (const float*)d_in[0];
    const float* w_qkv  = (const float*)d_in[1];
    const float* w_proj = (const float*)d_in[2];
    float* out = (float*)d_out;

    float *qkv, *ct, *st;
    __half *xh, *wqkvh, *wprojh, *qh, *kh, *vth, *atth;
    cudaGetSymbolAddress((void**)&qkv,    g_qkv);
    cudaGetSymbolAddress((void**)&ct,     g_ctab);
    cudaGetSymbolAddress((void**)&st,     g_stab);
    cudaGetSymbolAddress((void**)&xh,     g_xh);
    cudaGetSymbolAddress((void**)&wqkvh,  g_wqkvh);
    cudaGetSymbolAddress((void**)&wprojh, g_wprojh);
    cudaGetSymbolAddress((void**)&qh,     g_qh);
    cudaGetSymbolAddress((void**)&kh,     g_kh);
    cudaGetSymbolAddress((void**)&vth,    g_vth);
    cudaGetSymbolAddress((void**)&atth,   g_atth);

    cudaFuncSetAttribute(gemm_h,  cudaFuncAttributeMaxDynamicSharedMemorySize, GEMMH_SMEM);
    cudaFuncSetAttribute(flash_h, cudaFuncAttributeMaxDynamicSharedMemorySize, FLASHH_BYTES);

    build_tab<<<TSEQ, HD>>>(ct, st);

    round_half<<<(M1*(size_t)DIM)/(256*8), 256>>>(x, xh);
    round_half<<<((size_t)N_QKV*DIM)/(256*8), 256>>>(w_qkv, wqkvh);
    round_half<<<((size_t)DIM*DIM)/(256*8), 256>>>(w_proj, wprojh);

    gemm_h<<<dim3(N_QKV/BN, M1/BM), 128, GEMMH_SMEM>>>(xh, wqkvh, qkv, M1, N_QKV, DIM);

    rope_split<<<M1, 256>>>(qkv, ct, st, qh, kh);
    vtrans<<<dim3(TSEQ/32, HD/32, BATCH*NH), dim3(32, 8)>>>(qkv, vth);

    flash_h<<<dim3(TSEQ/FQ, BATCH*NH), 256, FLASHH_BYTES>>>(qh, kh, vth, atth);

    gemm_h<<<dim3(DIM/BN, M1/BM), 128, GEMMH_SMEM>>>(atth, wprojh, out, M1, DIM, DIM);
}

// round 15
// speedup vs baseline: 2.5032x; 1.0475x over previous
#include <cuda_runtime.h>
#include <cuda_fp16.h>
#include <math.h>
#include <stdint.h>

// Problem constants
#define BATCH 2
#define TSEQ  4096
#define DIM   2048
#define NH    16
#define HD    128
#define M1    (BATCH*TSEQ)      // 8192
#define N_QKV (3*DIM)           // 6144

// ---------------- scratch (static device globals; no allocs allowed) ----------
__device__ float  g_qkv[(size_t)M1 * N_QKV];           // fp32 qkv (GEMM1 out)
__device__ __half g_xh[(size_t)M1 * DIM];
__device__ __half g_wqkvh[(size_t)N_QKV * DIM];
__device__ __half g_wprojh[(size_t)DIM * DIM];
__device__ __half g_qh[(size_t)BATCH*NH*TSEQ*HD];      // [bh][t][d]
__device__ __half g_kh[(size_t)BATCH*NH*TSEQ*HD];      // [bh][t][d]
__device__ __half g_vth[(size_t)BATCH*NH*HD*TSEQ];     // [bh][d][t]  (transposed)
__device__ __half g_atth[(size_t)M1 * DIM];
__device__ float  g_ctab[(size_t)TSEQ * HD];
__device__ float  g_stab[(size_t)TSEQ * HD];

// ---------------- helpers -----------------------------------------------------
__device__ __forceinline__ void mma_f16(float* d, const uint32_t* a, const uint32_t* b) {
    asm volatile(
        "mma.sync.aligned.m16n8k16.row.col.f32.f16.f16.f32 "
        "{%0,%1,%2,%3}, {%4,%5,%6,%7}, {%8,%9}, {%0,%1,%2,%3};"
        : "+f"(d[0]), "+f"(d[1]), "+f"(d[2]), "+f"(d[3])
        : "r"(a[0]), "r"(a[1]), "r"(a[2]), "r"(a[3]), "r"(b[0]), "r"(b[1]));
}

__device__ __forceinline__ void ldsm_x4(uint32_t* r, uint32_t saddr) {
    asm volatile("ldmatrix.sync.aligned.m8n8.x4.shared.b16 {%0,%1,%2,%3}, [%4];"
        : "=r"(r[0]), "=r"(r[1]), "=r"(r[2]), "=r"(r[3]) : "r"(saddr));
}

__device__ __forceinline__ uint32_t smem_u32(const void* p) {
    uint32_t a;
    asm("{ .reg .u64 t; cvta.to.shared.u64 t, %1; cvt.u32.u64 %0, t; }" : "=r"(a) : "l"(p));
    return a;
}
__device__ __forceinline__ void cp_async16(uint32_t saddr, const void* gaddr) {
    asm volatile("cp.async.cg.shared.global [%0], [%1], 16;" :: "r"(saddr), "l"(gaddr));
}
#define CP_COMMIT() asm volatile("cp.async.commit_group;" ::: "memory")
#define CP_WAIT1()  asm volatile("cp.async.wait_group 1;" ::: "memory")
#define CP_WAIT2()  asm volatile("cp.async.wait_group 2;" ::: "memory")

__device__ __forceinline__ uint32_t h2u(__half2 h) {
    union { __half2 h; uint32_t u; } c; c.h = h; return c.u;
}

// ---------------- cos/sin table ----------------------------------------------
__global__ void build_tab(float* __restrict__ ct, float* __restrict__ st) {
    int t = blockIdx.x;
    int j = threadIdx.x;
    int m = j & 63;
    float base = (float)pow(10000.0, (double)m / 64.0);
    float invf = 1.0f / base;
    float ang = (float)t * invf;
    ct[t*HD + j] = cosf(ang);
    st[t*HD + j] = sinf(ang);
}

// ---------------- fp32 -> fp16 pass (8 elems/thread) --------------------------
__global__ void round_half(const float* __restrict__ in, __half* __restrict__ out) {
    size_t i = ((size_t)blockIdx.x * 256 + threadIdx.x) * 8;
    float4 v0 = *(const float4*)(in + i);
    float4 v1 = *(const float4*)(in + i + 4);
    uint4 u;
    u.x = h2u(__floats2half2_rn(v0.x, v0.y));
    u.y = h2u(__floats2half2_rn(v0.z, v0.w));
    u.z = h2u(__floats2half2_rn(v1.x, v1.y));
    u.w = h2u(__floats2half2_rn(v1.z, v1.w));
    *(uint4*)(out + i) = u;
}

// ---------------- fp16 cp.async pipelined GEMM: C = A * B^T -------------------
// 128x128 CTA tile, 4 warps (2x2) of 64x64, BK=32, 4 stages, 128 threads.
#define BM 128
#define BN 128
#define BKH 32
#define STAGES 4
#define HSTR 40
#define GEMMH_SMEM (STAGES * (BM + BN) * HSTR * 2)    // 81920 B

__global__ __launch_bounds__(128, 2) void gemm_h(
    const __half* __restrict__ A, const __half* __restrict__ B,
    float* __restrict__ C, int M, int N, int K)
{
    extern __shared__ __half hsm[];
    uint32_t sbase = smem_u32(hsm);
    const uint32_t boff = STAGES * BM * HSTR;          // halves

    int tid  = threadIdx.x;
    int wid  = tid >> 5, lane = tid & 31;
    int g    = lane >> 2, tg = lane & 3;
    int wm   = wid >> 1, wn = wid & 1;
    int m0   = blockIdx.y * BM;
    int n0   = blockIdx.x * BN;

    int la_row = lane & 15;
    int la_k   = (lane >> 4) << 3;
    int lb_row = ((lane >> 4) << 3) + (lane & 7);
    int lb_k   = ((lane >> 3) & 1) << 3;

    float acc[4][8][4];
#pragma unroll
    for (int i = 0; i < 4; i++)
#pragma unroll
        for (int j = 0; j < 8; j++)
#pragma unroll
            for (int r = 0; r < 4; r++) acc[i][j][r] = 0.f;

    const int nch = K / BKH;

    auto issue = [&](int ch, bool pred) {
        if (pred) {
            int s = ch % STAGES;
            const __half* Ag = A + (size_t)m0 * K + ch * BKH;
            const __half* Bg = B + (size_t)n0 * K + ch * BKH;
            uint32_t as = sbase + (uint32_t)(s * BM * HSTR) * 2u;
            uint32_t bs = sbase + (boff + (uint32_t)(s * BN * HSTR)) * 2u;
#pragma unroll
            for (int e = 0; e < 4; e++) {
                int idx = tid + e * 128;
                int r  = idx >> 2;
                int c8 = (idx & 3) << 3;
                cp_async16(as + (uint32_t)(r * HSTR + c8) * 2u, Ag + (size_t)r * K + c8);
                cp_async16(bs + (uint32_t)(r * HSTR + c8) * 2u, Bg + (size_t)r * K + c8);
            }
        }
        CP_COMMIT();
    };

    issue(0, true);
    issue(1, 1 < nch);
    issue(2, 2 < nch);

    for (int ch = 0; ch < nch; ch++) {
        CP_WAIT2();
        __syncthreads();
        issue(ch + 3, ch + 3 < nch);

        int s = ch % STAGES;
        uint32_t asad = sbase + (uint32_t)(s * BM * HSTR) * 2u;
        uint32_t bsad = sbase + (boff + (uint32_t)(s * BN * HSTR)) * 2u;

#pragma unroll
        for (int ks = 0; ks < BKH; ks += 16) {
            uint32_t afr[4][4];
#pragma unroll
            for (int mi = 0; mi < 4; mi++) {
                int mr = wm * 64 + mi * 16;
                ldsm_x4(afr[mi], asad + (uint32_t)((mr + la_row) * HSTR + ks + la_k) * 2u);
            }
            uint32_t bfr[8][2];
#pragma unroll
            for (int p = 0; p < 4; p++) {
                int nr2 = wn * 64 + p * 16;
                uint32_t r4[4];
                ldsm_x4(r4, bsad + (uint32_t)((nr2 + lb_row) * HSTR + ks + lb_k) * 2u);
                bfr[2*p  ][0] = r4[0]; bfr[2*p  ][1] = r4[1];
                bfr[2*p+1][0] = r4[2]; bfr[2*p+1][1] = r4[3];
            }
#pragma unroll
            for (int mi = 0; mi < 4; mi++)
#pragma unroll
                for (int nj = 0; nj < 8; nj++)
                    mma_f16(acc[mi][nj], afr[mi], bfr[nj]);
        }
    }

#pragma unroll
    for (int mi = 0; mi < 4; mi++) {
#pragma unroll
        for (int nj = 0; nj < 8; nj++) {
            int row = m0 + wm * 64 + mi * 16 + g;
            int col = n0 + wn * 64 + nj * 8 + tg * 2;
            *(float2*)(C + (size_t)row * N + col) =
                make_float2(acc[mi][nj][0], acc[mi][nj][1]);
            *(float2*)(C + (size_t)(row + 8) * N + col) =
                make_float2(acc[mi][nj][2], acc[mi][nj][3]);
        }
    }
}

// ---------------- RoPE + head split -> half Q,K (vectorized) -----------------
__global__ void rope_split(const float* __restrict__ qkv,
                           const float* __restrict__ ct, const float* __restrict__ st,
                           __half* __restrict__ Qo, __half* __restrict__ Ko)
{
    int bt  = blockIdx.x;
    int tid = threadIdx.x;           // 256
    int j2  = tid & 63;
    int hh  = tid >> 6;
    int b   = bt >> 12;
    int t   = bt & (TSEQ - 1);
    int j   = 2 * j2;

    float2 c = *(const float2*)(ct + t*HD + j);
    float2 s = *(const float2*)(st + t*HD + j);

#pragma unroll
    for (int e = 0; e < 4; e++) {
        int h = hh + e * 4;
        size_t base = (size_t)bt * N_QKV + h * HD + j;
        float2 xq = *(const float2*)(qkv + base);
        float2 xk = *(const float2*)(qkv + base + DIM);
        float oq0 = xq.x * c.x - xq.y * s.x;
        float oq1 = xq.y * c.y + xq.x * s.y;
        float ok0 = xk.x * c.x - xk.y * s.x;
        float ok1 = xk.y * c.y + xk.x * s.y;
        size_t ob = ((size_t)(b*NH + h) * TSEQ + t) * HD + j;
        *(__half2*)(Qo + ob) = __floats2half2_rn(oq0, oq1);
        *(__half2*)(Ko + ob) = __floats2half2_rn(ok0, ok1);
    }
}

// ---------------- V transpose: qkv -> Vt[bh][d][t] (half) --------------------
__global__ void vtrans(const float* __restrict__ qkv, __half* __restrict__ Vt) {
    __shared__ float tile[32][33];
    int bh = blockIdx.z;
    int b  = bh >> 4, h = bh & 15;
    int t0 = blockIdx.x * 32;
    int d0 = blockIdx.y * 32;
    int tx = threadIdx.x, ty = threadIdx.y;   // 32 x 8

#pragma unroll
    for (int i = 0; i < 4; i++) {
        int t = t0 + ty + i * 8;
        tile[ty + i*8][tx] = qkv[(size_t)(b*TSEQ + t) * N_QKV + 2*DIM + h*HD + d0 + tx];
    }
    __syncthreads();
#pragma unroll
    for (int i = 0; i < 4; i++) {
        int d = d0 + ty + i * 8;
        Vt[((size_t)bh * HD + d) * TSEQ + t0 + tx] = __float2half(tile[tx][ty + i*8]);
    }
}

// ---------------- fp16 mma flash attention (causal, FK=128) ------------------
// Q tile 128, K tile 128, 8 warps; warp = 16 Q rows x full K width.
#define FQ 128
#define FK 128
#define QSTR 136       // halves
#define KSTR 136
#define VSTR 136
#define PSTR 136
#define OFF_Q  0
#define OFF_K0 (OFF_Q  + FQ*QSTR)     // 17408
#define OFF_K1 (OFF_K0 + FK*KSTR)     // 34816
#define OFF_V  (OFF_K1 + FK*KSTR)     // 52224
#define OFF_P  (OFF_V  + HD*VSTR)     // 69632
#define FLASHH_HALVES (OFF_P + FQ*PSTR)   // 87040
#define FLASHH_BYTES (FLASHH_HALVES * 2)  // 174080

__global__ __launch_bounds__(256, 1) void flash_h(
    const __half* __restrict__ Q, const __half* __restrict__ K,
    const __half* __restrict__ Vt, __half* __restrict__ Oatt)
{
    extern __shared__ __half hs[];
    __half* Ps = hs + OFF_P;
    uint32_t sbase = smem_u32(hs);

    int qi  = blockIdx.x;
    int bh  = blockIdx.y;
    int tid = threadIdx.x;
    int w    = tid >> 5;
    int lane = tid & 31;
    int g    = lane >> 2;
    int tg   = lane & 3;

    int la_row = lane & 15;
    int la_k   = (lane >> 4) << 3;
    int lb_row = ((lane >> 4) << 3) + (lane & 7);
    int lb_k   = ((lane >> 3) & 1) << 3;

    const __half* Qp  = Q  + (size_t)bh * TSEQ * HD;
    const __half* Kp  = K  + (size_t)bh * TSEQ * HD;
    const __half* Vtp = Vt + (size_t)bh * HD * TSEQ;

    int q0 = qi * FQ;
    int nkt = qi + 1;

    // K tile: [128][128] half = 2048 x 16B chunks, 8/thread
    auto issueK = [&](int kt, bool pred) {
        if (pred) {
            int k0 = kt * FK;
            uint32_t kb = sbase + (uint32_t)((kt & 1) ? OFF_K1 : OFF_K0) * 2u;
#pragma unroll
            for (int e = 0; e < 8; e++) {
                int idx = tid + e * 256;
                int r  = idx >> 4;
                int c8 = (idx & 15) << 3;
                cp_async16(kb + (uint32_t)(r * KSTR + c8) * 2u,
                           Kp + (size_t)(k0 + r) * HD + c8);
            }
        }
        CP_COMMIT();
    };
    // V tile transposed: [128 d][128 t] = 2048 chunks, 8/thread
    auto issueV = [&](int kt) {
        int k0 = kt * FK;
        uint32_t vb = sbase + (uint32_t)OFF_V * 2u;
#pragma unroll
        for (int e = 0; e < 8; e++) {
            int idx = tid + e * 256;
            int d  = idx >> 4;
            int c8 = (idx & 15) << 3;
            cp_async16(vb + (uint32_t)(d * VSTR + c8) * 2u,
                       Vtp + (size_t)d * TSEQ + k0 + c8);
        }
        CP_COMMIT();
    };

    issueK(0, true);

    // load Q tile
#pragma unroll
    for (int e = 0; e < 8; e++) {
        int idx = tid + e * 256;
        int r  = idx >> 4;
        int c8 = (idx & 15) << 3;
        uint4 v = *(const uint4*)(Qp + (size_t)(q0 + r) * HD + c8);
        *(uint4*)(hs + OFF_Q + r * QSTR + c8) = v;
    }

    float o[16][4];
#pragma unroll
    for (int i = 0; i < 16; i++)
#pragma unroll
        for (int j = 0; j < 4; j++) o[i][j] = 0.f;

    float m0r = -1e30f, m1r = -1e30f;
    float l0 = 0.f, l1 = 0.f;
    const float scale = 0.08838834764831845f;   // 1/sqrt(128)

    int rowbase = q0 + w * 16;
    int r0g = rowbase + g;
    int r1g = rowbase + g + 8;
    int rq = rowbase - q0;

    uint32_t qad   = sbase + (uint32_t)(OFF_Q + (rq + la_row) * QSTR + la_k) * 2u;
    uint32_t pad_a = sbase + (uint32_t)(OFF_P + (rq + la_row) * PSTR + la_k) * 2u;

    float s[16][4];

    for (int kt = 0; kt < nkt; kt++) {
        int k0 = kt * FK;
        uint32_t kad = sbase + (uint32_t)(((kt & 1) ? OFF_K1 : OFF_K0) + lb_row * KSTR + lb_k) * 2u;

        issueV(kt);
        issueK(kt + 1, kt + 1 < nkt);
        CP_WAIT2();                 // K(kt) done; V(kt), K(kt+1) in flight
        __syncthreads();

        // ---- S = Q K^T : 8 ks steps of k=16, 16 column tiles ----
#pragma unroll
        for (int nj = 0; nj < 16; nj++)
#pragma unroll
            for (int r = 0; r < 4; r++) s[nj][r] = 0.f;

#pragma unroll
        for (int ks = 0; ks < 8; ks++) {
            uint32_t a[4];
            ldsm_x4(a, qad + (uint32_t)(ks * 16) * 2u);
            uint32_t bfr[16][2];
#pragma unroll
            for (int p = 0; p < 8; p++) {
                uint32_t r4[4];
                ldsm_x4(r4, kad + (uint32_t)(p * 16 * KSTR + ks * 16) * 2u);
                bfr[2*p  ][0] = r4[0]; bfr[2*p  ][1] = r4[1];
                bfr[2*p+1][0] = r4[2]; bfr[2*p+1][1] = r4[3];
            }
#pragma unroll
            for (int nj = 0; nj < 16; nj++)
                mma_f16(s[nj], a, bfr[nj]);
        }

        // ---- causal mask (only the diagonal tile) ----
        if (k0 + FK - 1 > rowbase) {
#pragma unroll
            for (int nj = 0; nj < 16; nj++) {
                int c = k0 + nj*8 + 2*tg;
                if (c     > r0g) s[nj][0] = -1e30f;
                if (c + 1 > r0g) s[nj][1] = -1e30f;
                if (c     > r1g) s[nj][2] = -1e30f;
                if (c + 1 > r1g) s[nj][3] = -1e30f;
            }
        }

        // ---- online softmax (warp-local, quad reductions) ----
        float mx0 = -1e30f, mx1 = -1e30f;
#pragma unroll
        for (int nj = 0; nj < 16; nj++) {
            mx0 = fmaxf(mx0, fmaxf(s[nj][0], s[nj][1]));
            mx1 = fmaxf(mx1, fmaxf(s[nj][2], s[nj][3]));
        }
        mx0 = fmaxf(mx0, __shfl_xor_sync(0xffffffff, mx0, 1));
        mx0 = fmaxf(mx0, __shfl_xor_sync(0xffffffff, mx0, 2));
        mx1 = fmaxf(mx1, __shfl_xor_sync(0xffffffff, mx1, 1));
        mx1 = fmaxf(mx1, __shfl_xor_sync(0xffffffff, mx1, 2));

        float mn0 = fmaxf(m0r, mx0);
        float mn1 = fmaxf(m1r, mx1);
        float al0 = __expf((m0r - mn0) * scale);
        float al1 = __expf((m1r - mn1) * scale);
        m0r = mn0; m1r = mn1;

        float sum0 = 0.f, sum1 = 0.f;
#pragma unroll
        for (int nj = 0; nj < 16; nj++) {
            float p0 = __expf((s[nj][0] - mn0) * scale);
            float p1 = __expf((s[nj][1] - mn0) * scale);
            float p2 = __expf((s[nj][2] - mn1) * scale);
            float p3 = __expf((s[nj][3] - mn1) * scale);
            s[nj][0] = p0; s[nj][1] = p1; s[nj][2] = p2; s[nj][3] = p3;
            sum0 += p0 + p1; sum1 += p2 + p3;
        }
        sum0 += __shfl_xor_sync(0xffffffff, sum0, 1);
        sum0 += __shfl_xor_sync(0xffffffff, sum0, 2);
        sum1 += __shfl_xor_sync(0xffffffff, sum1, 1);
        sum1 += __shfl_xor_sync(0xffffffff, sum1, 2);

        l0 = l0 * al0 + sum0;
        l1 = l1 * al1 + sum1;

#pragma unroll
        for (int t2 = 0; t2 < 16; t2++) {
            o[t2][0] *= al0; o[t2][1] *= al0;
            o[t2][2] *= al1; o[t2][3] *= al1;
        }

        // ---- write P (half2 pairs) ----
        int pr0 = (rq + g) * PSTR;
        int pr1 = (rq + g + 8) * PSTR;
#pragma unroll
        for (int nj = 0; nj < 16; nj++) {
            int c = nj*8 + 2*tg;
            *(__half2*)(Ps + pr0 + c) = __floats2half2_rn(s[nj][0], s[nj][1]);
            *(__half2*)(Ps + pr1 + c) = __floats2half2_rn(s[nj][2], s[nj][3]);
        }

        CP_WAIT1();                 // V(kt) done; K(kt+1) may be in flight
        __syncthreads();

        // ---- O += P V : 8 ks2 steps of k=16 tokens, 16 d-tiles ----
        uint32_t vad = sbase + (uint32_t)(OFF_V + lb_row * VSTR + lb_k) * 2u;
#pragma unroll
        for (int ks2 = 0; ks2 < 8; ks2++) {
            uint32_t a2[4];
            ldsm_x4(a2, pad_a + (uint32_t)(ks2 * 16) * 2u);
#pragma unroll
            for (int p = 0; p < 8; p++) {
                uint32_t r4[4];
                ldsm_x4(r4, vad + (uint32_t)(p * 16 * VSTR + ks2 * 16) * 2u);
                uint32_t b0[2] = { r4[0], r4[1] };
                uint32_t b1[2] = { r4[2], r4[3] };
                mma_f16(o[2*p  ], a2, b0);
                mma_f16(o[2*p+1], a2, b1);
            }
        }
        __syncthreads();            // V buffer + K stage free for next iter
    }

    // epilogue: normalize + write att as half (proj GEMM A operand)
    float inv0 = 1.0f / l0;
    float inv1 = 1.0f / l1;
    int b = bh >> 4, h = bh & 15;
#pragma unroll
    for (int nj2 = 0; nj2 < 16; nj2++) {
        int col = h * HD + nj2*8 + 2*tg;
        *(__half2*)(Oatt + (size_t)(b*TSEQ + r0g) * DIM + col) =
            __floats2half2_rn(o[nj2][0] * inv0, o[nj2][1] * inv0);
        *(__half2*)(Oatt + (size_t)(b*TSEQ + r1g) * DIM + col) =
            __floats2half2_rn(o[nj2][2] * inv1, o[nj2][3] * inv1);
    }
}

// ---------------- launch ------------------------------------------------------
extern "C" void kernel_launch(void* const* d_in, const int* in_sizes, int n_in,
                              void* d_out, int out_size) {
    const float* x      = (const float*)d_in[0];
    const float* w_qkv  = (const float*)d_in[1];
    const float* w_proj = (const float*)d_in[2];
    float* out = (float*)d_out;

    float *qkv, *ct, *st;
    __half *xh, *wqkvh, *wprojh, *qh, *kh, *vth, *atth;
    cudaGetSymbolAddress((void**)&qkv,    g_qkv);
    cudaGetSymbolAddress((void**)&ct,     g_ctab);
    cudaGetSymbolAddress((void**)&st,     g_stab);
    cudaGetSymbolAddress((void**)&xh,     g_xh);
    cudaGetSymbolAddress((void**)&wqkvh,  g_wqkvh);
    cudaGetSymbolAddress((void**)&wprojh, g_wprojh);
    cudaGetSymbolAddress((void**)&qh,     g_qh);
    cudaGetSymbolAddress((void**)&kh,     g_kh);
    cudaGetSymbolAddress((void**)&vth,    g_vth);
    cudaGetSymbolAddress((void**)&atth,   g_atth);

    cudaFuncSetAttribute(gemm_h,  cudaFuncAttributeMaxDynamicSharedMemorySize, GEMMH_SMEM);
    cudaFuncSetAttribute(flash_h, cudaFuncAttributeMaxDynamicSharedMemorySize, FLASHH_BYTES);

    build_tab<<<TSEQ, HD>>>(ct, st);

    round_half<<<(M1*(size_t)DIM)/(256*8), 256>>>(x, xh);
    round_half<<<((size_t)N_QKV*DIM)/(256*8), 256>>>(w_qkv, wqkvh);
    round_half<<<((size_t)DIM*DIM)/(256*8), 256>>>(w_proj, wprojh);

    gemm_h<<<dim3(N_QKV/BN, M1/BM), 128, GEMMH_SMEM>>>(xh, wqkvh, qkv, M1, N_QKV, DIM);

    rope_split<<<M1, 256>>>(qkv, ct, st, qh, kh);
    vtrans<<<dim3(TSEQ/32, HD/32, BATCH*NH), dim3(32, 8)>>>(qkv, vth);

    flash_h<<<dim3(TSEQ/FQ, BATCH*NH), 256, FLASHH_BYTES>>>(qh, kh, vth, atth);

    gemm_h<<<dim3(DIM/BN, M1/BM), 128, GEMMH_SMEM>>>(atth, wprojh, out, M1, DIM, DIM);
}